// round 1
// baseline (speedup 1.0000x reference)
#include <cuda_runtime.h>
#include <math.h>

#define BB 2
#define LL 1024
#define DM 768
#define NLAYER 2
#define DI 1536
#define NS 16
#define DTR 48
#define XD 80           // DTR + 2*NS
#define SS 4            // augmented batch: [fwd b0, fwd b1, bwd b0, bwd b1]
#define M4 (SS*LL)      // 4096 GEMM rows

// ---------------- scratch (static __device__, no allocation) ----------------
__device__ __align__(128) float g_h[BB*LL*DM];
__device__ __align__(128) float g_res[BB*LL*DM];
__device__ __align__(128) float g_resA[SS*LL*DM];
__device__ __align__(128) float g_x[SS*LL*DM];
__device__ __align__(128) float g_xz[SS*LL*2*DI];
__device__ __align__(128) float g_xc[SS*LL*DI];
__device__ __align__(128) float g_xdbl[SS*LL*XD];
__device__ __align__(128) float g_delta[SS*LL*DI];
__device__ __align__(128) float g_y[SS*LL*DI];
__device__ __align__(128) float g_g[SS*LL*DI];
__device__ __align__(128) float g_bo[SS*LL*DM];
__device__ __align__(128) float g_fin[BB*LL*DM];

__device__ __forceinline__ float siluf(float x){ return x/(1.f+__expf(-x)); }

// ---------------- elementwise kernels ----------------
__global__ void embed_kernel(const int* __restrict__ ids, const float* __restrict__ emb,
                             float* __restrict__ out){
  int i = blockIdx.x*blockDim.x+threadIdx.x;
  if(i>=BB*LL*DM) return;
  int d=i%DM; int t=i/DM;
  out[i] = emb[(size_t)ids[t]*DM + d];
}

// resA[s] = h(+res) for s<2, reversed copy for s>=2
__global__ void augment_kernel(const float* __restrict__ h, const float* __restrict__ res,
                               float* __restrict__ resA, int use_res){
  int i = blockIdx.x*blockDim.x+threadIdx.x;
  if(i>=BB*LL*DM) return;
  int d=i%DM; int l=(i/DM)%LL; int b=i/(DM*LL);
  float v=h[i]; if(use_res) v+=res[i];
  resA[((size_t)(b*LL+l))*DM+d]=v;
  resA[((size_t)((2+b)*LL+(LL-1-l)))*DM+d]=v;
}

// Row LayerNorm over DM=768, 256 threads, optional pre-add and sum writeback.
__global__ void ln_kernel(const float* __restrict__ in, const float* __restrict__ addin,
                          float* __restrict__ sumout, float* __restrict__ out,
                          const float* __restrict__ w, const float* __restrict__ bias){
  int r = blockIdx.x;
  size_t base = (size_t)r*DM;
  float v[3]; float s=0.f,s2=0.f;
  #pragma unroll
  for(int j=0;j<3;j++){
    int idx = threadIdx.x + j*256;
    float t = in[base+idx];
    if(addin) t += addin[base+idx];
    v[j]=t; s+=t; s2+=t*t;
  }
  if(sumout){
    #pragma unroll
    for(int j=0;j<3;j++) sumout[base+threadIdx.x+j*256]=v[j];
  }
  #pragma unroll
  for(int o=16;o>0;o>>=1){ s+=__shfl_xor_sync(0xffffffffu,s,o); s2+=__shfl_xor_sync(0xffffffffu,s2,o); }
  __shared__ float sh[2][8];
  int wid=threadIdx.x>>5, lane=threadIdx.x&31;
  if(lane==0){ sh[0][wid]=s; sh[1][wid]=s2; }
  __syncthreads();
  if(threadIdx.x<32){
    float a = lane<8? sh[0][lane]:0.f;
    float b2= lane<8? sh[1][lane]:0.f;
    #pragma unroll
    for(int o=4;o>0;o>>=1){ a+=__shfl_xor_sync(0xffffffffu,a,o); b2+=__shfl_xor_sync(0xffffffffu,b2,o); }
    if(lane==0){ sh[0][0]=a; sh[1][0]=b2; }
  }
  __syncthreads();
  float mean = sh[0][0]*(1.f/DM);
  float var  = fmaxf(sh[1][0]*(1.f/DM) - mean*mean, 0.f);
  float inv  = rsqrtf(var + 1e-5f);
  #pragma unroll
  for(int j=0;j<3;j++){
    int idx = threadIdx.x + j*256;
    out[base+idx] = (v[j]-mean)*inv*w[idx] + bias[idx];
  }
}

// depthwise causal conv (K=4) + silu; input = first half of xz rows
__global__ void conv_silu_kernel(const float* __restrict__ xz, const float* __restrict__ w,
                                 const float* __restrict__ b, float* __restrict__ xc){
  int i = blockIdx.x*blockDim.x+threadIdx.x;
  if(i>=SS*LL*DI) return;
  int d=i%DI; int l=(i/DI)%LL; int s=i/(DI*LL);
  const float* xin = xz + (size_t)s*LL*2*DI + d;
  float acc = b[d];
  #pragma unroll
  for(int j=0;j<4;j++){
    int ll=l-3+j;
    if(ll>=0) acc = fmaf(w[d*4+j], xin[(size_t)ll*2*DI], acc);
  }
  xc[i] = siluf(acc);
}

// selective scan: one thread per (s,d) channel, 16 states in registers
__global__ void scan_kernel(const float* __restrict__ xc, const float* __restrict__ delta,
                            const float* __restrict__ xdbl, const float* __restrict__ A_log,
                            const float* __restrict__ Dp, float* __restrict__ y){
  int idx = blockIdx.x*blockDim.x+threadIdx.x;
  if(idx>=SS*DI) return;
  int d = idx%DI; int s = idx/DI;
  float Ar[NS];
  #pragma unroll
  for(int n=0;n<NS;n++) Ar[n] = -__expf(A_log[d*NS+n]);
  float Dv = Dp[d];
  float h[NS];
  #pragma unroll
  for(int n=0;n<NS;n++) h[n]=0.f;
  const float* up = xc    + (size_t)s*LL*DI + d;
  const float* dp = delta + (size_t)s*LL*DI + d;
  const float* xd = xdbl  + (size_t)s*LL*XD;
  float* yp       = y     + (size_t)s*LL*DI + d;
  for(int l=0;l<LL;l++){
    float dl = dp[(size_t)l*DI];
    float u  = up[(size_t)l*DI];
    float du = dl*u;
    const float4* Bm = (const float4*)(xd + (size_t)l*XD + DTR);
    const float4* Cm = (const float4*)(xd + (size_t)l*XD + DTR + NS);
    float out = 0.f;
    #pragma unroll
    for(int q=0;q<4;q++){
      float4 b4 = Bm[q];
      float4 c4 = Cm[q];
      float e;
      e=__expf(dl*Ar[4*q+0]); h[4*q+0]=fmaf(e,h[4*q+0],du*b4.x); out=fmaf(h[4*q+0],c4.x,out);
      e=__expf(dl*Ar[4*q+1]); h[4*q+1]=fmaf(e,h[4*q+1],du*b4.y); out=fmaf(h[4*q+1],c4.y,out);
      e=__expf(dl*Ar[4*q+2]); h[4*q+2]=fmaf(e,h[4*q+2],du*b4.z); out=fmaf(h[4*q+2],c4.z,out);
      e=__expf(dl*Ar[4*q+3]); h[4*q+3]=fmaf(e,h[4*q+3],du*b4.w); out=fmaf(h[4*q+3],c4.w,out);
    }
    yp[(size_t)l*DI] = fmaf(u, Dv, out);
  }
}

__global__ void gate_mul_kernel(float* __restrict__ y, const float* __restrict__ xz){
  int i=blockIdx.x*blockDim.x+threadIdx.x;
  if(i>=SS*LL*DI) return;
  int r=i/DI, j=i%DI;
  float z = xz[(size_t)r*2*DI + DI + j];
  y[i] *= siluf(z);
}

__global__ void fc_gate_kernel(const float* __restrict__ big, float* __restrict__ g){
  int i=blockIdx.x*blockDim.x+threadIdx.x;
  if(i>=SS*LL*DI) return;
  int r=i/DI, j=i%DI;
  float a = big[(size_t)r*2*DI + j];
  float b = big[(size_t)r*2*DI + DI + j];
  g[i] = a*siluf(b);
}

// h = LNf(bo)[fwd] + reverse(LNf(bo)[bwd]); res = resA[fwd] + reverse(resA[bwd])
__global__ void combine_kernel(const float* __restrict__ lnx, const float* __restrict__ resA,
                               float* __restrict__ h, float* __restrict__ res){
  int i=blockIdx.x*blockDim.x+threadIdx.x;
  if(i>=BB*LL*DM) return;
  int d=i%DM; int l=(i/DM)%LL; int b=i/(DM*LL);
  size_t f = ((size_t)(b*LL+l))*DM+d;
  size_t r = ((size_t)((2+b)*LL+(LL-1-l)))*DM+d;
  h[i]   = lnx[f]+lnx[r];
  res[i] = resA[f]+resA[r];
}

__global__ void mean_kernel(const float* __restrict__ fin, float* __restrict__ out){
  int i=blockIdx.x*blockDim.x+threadIdx.x;
  if(i>=BB*DM) return;
  int b=i/DM, j=i%DM;
  float s=0.f;
  for(int l=0;l<LL;l++) s += fin[((size_t)(b*LL+l))*DM+j];
  out[i] = s*(1.f/LL);
}

// ---------------- GEMM: C[M,N] = A[M,K](lda) * B[N,K]^T (+bias, +act) ----------------
// act: 0 = none, 1 = softplus
template<int BM,int BN,int TM,int TN,int BK>
__global__ void __launch_bounds__(256) gemm_nt(
    int M,int N,int K,int lda,
    const float* __restrict__ A, const float* __restrict__ Bw,
    float* __restrict__ C, const float* __restrict__ bias, int act)
{
  __shared__ float As[BK][BM];
  __shared__ float Bs[BK][BN];
  const int t  = threadIdx.x;
  const int bm = blockIdx.y*BM, bn = blockIdx.x*BN;
  const int TCOL = BN/TN;
  const int tx = t % TCOL, ty = t / TCOL;
  const int KQ = BK/4;
  float acc[TM][TN];
  #pragma unroll
  for(int i=0;i<TM;i++)
    #pragma unroll
    for(int j=0;j<TN;j++) acc[i][j]=0.f;

  for(int k0=0;k0<K;k0+=BK){
    for(int i=t;i<BM*KQ;i+=256){
      int row = i/KQ, kq = (i%KQ)*4;
      float4 v = *(const float4*)(A + (size_t)(bm+row)*lda + k0 + kq);
      As[kq][row]=v.x; As[kq+1][row]=v.y; As[kq+2][row]=v.z; As[kq+3][row]=v.w;
    }
    for(int i=t;i<BN*KQ;i+=256){
      int row = i/KQ, kq = (i%KQ)*4;
      int gn = bn+row;
      float4 v = make_float4(0.f,0.f,0.f,0.f);
      if(gn<N) v = *(const float4*)(Bw + (size_t)gn*K + k0 + kq);
      Bs[kq][row]=v.x; Bs[kq+1][row]=v.y; Bs[kq+2][row]=v.z; Bs[kq+3][row]=v.w;
    }
    __syncthreads();
    #pragma unroll
    for(int kk=0;kk<BK;kk++){
      float a[TM], b[TN];
      #pragma unroll
      for(int i=0;i<TM;i++) a[i]=As[kk][ty*TM+i];
      #pragma unroll
      for(int j=0;j<TN;j++) b[j]=Bs[kk][tx*TN+j];
      #pragma unroll
      for(int i=0;i<TM;i++)
        #pragma unroll
        for(int j=0;j<TN;j++) acc[i][j] = fmaf(a[i],b[j],acc[i][j]);
    }
    __syncthreads();
  }
  #pragma unroll
  for(int i=0;i<TM;i++){
    int gm = bm + ty*TM + i;
    #pragma unroll
    for(int j=0;j<TN;j++){
      int gn = bn + tx*TN + j;
      if(gn<N){
        float c = acc[i][j];
        if(bias) c += bias[gn];
        if(act==1) c = (c>20.f)? c : log1pf(__expf(c));
        C[(size_t)gm*N + gn] = c;
      }
    }
  }
}

// ---------------- launcher ----------------
extern "C" void kernel_launch(void* const* d_in, const int* in_sizes, int n_in,
                              void* d_out, int out_size){
  const int*   ids    = (const int*)  d_in[0];
  const float* emb    = (const float*)d_in[1];
  const float* norm_w = (const float*)d_in[2];
  const float* norm_b = (const float*)d_in[3];
  const float* in_proj= (const float*)d_in[4];
  const float* conv_w = (const float*)d_in[5];
  const float* conv_b = (const float*)d_in[6];
  const float* x_proj = (const float*)d_in[7];
  const float* dt_w   = (const float*)d_in[8];
  const float* dt_b   = (const float*)d_in[9];
  const float* A_log  = (const float*)d_in[10];
  const float* Dw     = (const float*)d_in[11];
  const float* out_proj=(const float*)d_in[12];
  const float* norm2_w= (const float*)d_in[13];
  const float* norm2_b= (const float*)d_in[14];
  const float* fc1    = (const float*)d_in[15];
  const float* fc2    = (const float*)d_in[16];
  const float* normf_w= (const float*)d_in[17];
  const float* normf_b= (const float*)d_in[18];
  float* out = (float*)d_out;

  float *p_h,*p_res,*p_resA,*p_x,*p_xz,*p_xc,*p_xdbl,*p_delta,*p_y,*p_g,*p_bo,*p_fin;
  cudaGetSymbolAddress((void**)&p_h,    g_h);
  cudaGetSymbolAddress((void**)&p_res,  g_res);
  cudaGetSymbolAddress((void**)&p_resA, g_resA);
  cudaGetSymbolAddress((void**)&p_x,    g_x);
  cudaGetSymbolAddress((void**)&p_xz,   g_xz);
  cudaGetSymbolAddress((void**)&p_xc,   g_xc);
  cudaGetSymbolAddress((void**)&p_xdbl, g_xdbl);
  cudaGetSymbolAddress((void**)&p_delta,g_delta);
  cudaGetSymbolAddress((void**)&p_y,    g_y);
  cudaGetSymbolAddress((void**)&p_g,    g_g);
  cudaGetSymbolAddress((void**)&p_bo,   g_bo);
  cudaGetSymbolAddress((void**)&p_fin,  g_fin);

  const int TP=256;
  embed_kernel<<<(BB*LL*DM+TP-1)/TP,TP>>>(ids, emb, p_h);

  for(int li=0; li<NLAYER; li++){
    const float* nw = norm_w  + (size_t)li*DM;
    const float* nb = norm_b  + (size_t)li*DM;
    const float* ip = in_proj + (size_t)li*2*DI*DM;
    const float* cw = conv_w  + (size_t)li*DI*4;
    const float* cb = conv_b  + (size_t)li*DI;
    const float* xp = x_proj  + (size_t)li*XD*DI;
    const float* dw = dt_w    + (size_t)li*DI*DTR;
    const float* db = dt_b    + (size_t)li*DI;
    const float* al = A_log   + (size_t)li*DI*NS;
    const float* Dl = Dw      + (size_t)li*DI;
    const float* op = out_proj+ (size_t)li*DM*DI;
    const float* n2w= norm2_w + (size_t)li*DM;
    const float* n2b= norm2_b + (size_t)li*DM;
    const float* f1 = fc1     + (size_t)li*2*DI*DM;
    const float* f2 = fc2     + (size_t)li*DM*DI;

    // res = h (+ res); build augmented fwd/bwd batch
    augment_kernel<<<(BB*LL*DM+TP-1)/TP,TP>>>(p_h, p_res, p_resA, li>0);
    // x = LN(res)
    ln_kernel<<<M4,256>>>(p_resA, nullptr, nullptr, p_x, nw, nb);
    // xz = x @ in_proj^T  (4096 x 3072, K=768)
    dim3 gIn(2*DI/128, M4/128);
    gemm_nt<128,128,8,8,16><<<gIn,256>>>(M4, 2*DI, DM, DM, p_x, ip, p_xz, nullptr, 0);
    // xc = silu(causal depthwise conv(xin))
    conv_silu_kernel<<<(SS*LL*DI+TP-1)/TP,TP>>>(p_xz, cw, cb, p_xc);
    // x_dbl = xc @ x_proj^T  (4096 x 80, K=1536)
    dim3 gXd((XD+15)/16, M4/128);
    gemm_nt<128,16,8,1,16><<<gXd,256>>>(M4, XD, DI, DI, p_xc, xp, p_xdbl, nullptr, 0);
    // delta = softplus(dt @ dt_w^T + dt_b)  (4096 x 1536, K=48, lda=80)
    dim3 gDt(DI/128, M4/128);
    gemm_nt<128,128,8,8,16><<<gDt,256>>>(M4, DI, DTR, XD, p_xdbl, dw, p_delta, db, 1);
    // selective scan
    scan_kernel<<<(SS*DI+TP-1)/TP,TP>>>(p_xc, p_delta, p_xdbl, al, Dl, p_y);
    // y *= silu(z)
    gate_mul_kernel<<<(SS*LL*DI+TP-1)/TP,TP>>>(p_y, p_xz);
    // mixer_out = y @ out_proj^T  (4096 x 768, K=1536)
    dim3 gOut(DM/128, M4/128);
    gemm_nt<128,128,8,8,16><<<gOut,256>>>(M4, DM, DI, DI, p_y, op, p_bo, nullptr, 0);
    // res += mixer_out ; x2 = LN(res, norm2)
    ln_kernel<<<M4,256>>>(p_bo, p_resA, p_resA, p_x, n2w, n2b);
    // fc1: (4096 x 3072, K=768)
    gemm_nt<128,128,8,8,16><<<gIn,256>>>(M4, 2*DI, DM, DM, p_x, f1, p_xz, nullptr, 0);
    // gated MLP: g = y1 * silu(gate)
    fc_gate_kernel<<<(SS*LL*DI+TP-1)/TP,TP>>>(p_xz, p_g);
    // fc2: (4096 x 768, K=1536)
    gemm_nt<128,128,8,8,16><<<gOut,256>>>(M4, DM, DI, DI, p_g, f2, p_bo, nullptr, 0);
    // final norm on block outputs, then fwd+reverse(bwd) combine
    ln_kernel<<<M4,256>>>(p_bo, nullptr, nullptr, p_x, normf_w, normf_b);
    combine_kernel<<<(BB*LL*DM+TP-1)/TP,TP>>>(p_x, p_resA, p_h, p_res);
  }

  // res = h + res ; h = LN(res, normf); out = mean over L
  ln_kernel<<<BB*LL,256>>>(p_h, p_res, nullptr, p_fin, normf_w, normf_b);
  mean_kernel<<<(BB*DM+TP-1)/TP,TP>>>(p_fin, out);
}

// round 5
// speedup vs baseline: 1.5997x; 1.5997x over previous
#include <cuda_runtime.h>
#include <cuda_bf16.h>
#include <math.h>
#include <stdint.h>

#define BB 2
#define LL 1024
#define DM 768
#define NLAYER 2
#define DI 1536
#define NS 16
#define DTR 48
#define XD 80           // DTR + 2*NS
#define SS 4            // augmented batch: [fwd b0, fwd b1, bwd b0, bwd b1]
#define M4 (SS*LL)      // 4096 GEMM rows

// ---------------- scratch (static __device__, no allocation) ----------------
__device__ __align__(128) float g_h[BB*LL*DM];
__device__ __align__(128) float g_res[BB*LL*DM];
__device__ __align__(128) float g_resA[SS*LL*DM];
__device__ __align__(128) float g_x[SS*LL*DM];
__device__ __align__(128) float g_xz[SS*LL*2*DI];
__device__ __align__(128) float g_xc[SS*LL*DI];
__device__ __align__(128) float g_xdbl[SS*LL*XD];
__device__ __align__(128) float g_delta[SS*LL*DI];
__device__ __align__(128) float g_y[SS*LL*DI];
__device__ __align__(128) float g_bo[SS*LL*DM];
__device__ __align__(128) float g_fin[BB*LL*DM];

// split-bf16 activation/weight planes: [hi plane][lo plane], row-major
__device__ __align__(128) __nv_bfloat16 g_pa768 [2*M4*DM];
__device__ __align__(128) __nv_bfloat16 g_pa1536[2*M4*DI];
__device__ __align__(128) __nv_bfloat16 g_pw_in [NLAYER*2*(2*DI)*DM];
__device__ __align__(128) __nv_bfloat16 g_pw_fc1[NLAYER*2*(2*DI)*DM];
__device__ __align__(128) __nv_bfloat16 g_pw_out[NLAYER*2*DM*DI];
__device__ __align__(128) __nv_bfloat16 g_pw_fc2[NLAYER*2*DM*DI];

__device__ __forceinline__ float siluf(float x){ return x/(1.f+__expf(-x)); }

__device__ __forceinline__ void split_bf16(float v, __nv_bfloat16& h, __nv_bfloat16& l){
  h = __float2bfloat16(v);
  l = __float2bfloat16(v - __bfloat162float(h));
}

// ---------------- elementwise kernels ----------------
__global__ void embed_kernel(const int* __restrict__ ids, const float* __restrict__ emb,
                             float* __restrict__ out){
  int i = blockIdx.x*blockDim.x+threadIdx.x;
  if(i>=BB*LL*DM) return;
  int d=i%DM; int t=i/DM;
  out[i] = emb[(size_t)ids[t]*DM + d];
}

__global__ void augment_kernel(const float* __restrict__ h, const float* __restrict__ res,
                               float* __restrict__ resA, int use_res){
  int i = blockIdx.x*blockDim.x+threadIdx.x;
  if(i>=BB*LL*DM) return;
  int d=i%DM; int l=(i/DM)%LL; int b=i/(DM*LL);
  float v=h[i]; if(use_res) v+=res[i];
  resA[((size_t)(b*LL+l))*DM+d]=v;
  resA[((size_t)((2+b)*LL+(LL-1-l)))*DM+d]=v;
}

// Row LayerNorm over DM=768. Optional pre-add, optional fp32 sum writeback,
// optional fp32 out, optional packed split-bf16 out (planeN = plane elem count).
__global__ void ln_kernel(const float* __restrict__ in, const float* __restrict__ addin,
                          float* __restrict__ sumout, float* __restrict__ out,
                          __nv_bfloat16* __restrict__ pk, int planeN,
                          const float* __restrict__ w, const float* __restrict__ bias){
  int r = blockIdx.x;
  size_t base = (size_t)r*DM;
  float v[3]; float s=0.f,s2=0.f;
  #pragma unroll
  for(int j=0;j<3;j++){
    int idx = threadIdx.x + j*256;
    float t = in[base+idx];
    if(addin) t += addin[base+idx];
    v[j]=t; s+=t; s2+=t*t;
  }
  if(sumout){
    #pragma unroll
    for(int j=0;j<3;j++) sumout[base+threadIdx.x+j*256]=v[j];
  }
  #pragma unroll
  for(int o=16;o>0;o>>=1){ s+=__shfl_xor_sync(0xffffffffu,s,o); s2+=__shfl_xor_sync(0xffffffffu,s2,o); }
  __shared__ float sh[2][8];
  int wid=threadIdx.x>>5, lane=threadIdx.x&31;
  if(lane==0){ sh[0][wid]=s; sh[1][wid]=s2; }
  __syncthreads();
  if(threadIdx.x<32){
    float a = lane<8? sh[0][lane]:0.f;
    float b2= lane<8? sh[1][lane]:0.f;
    #pragma unroll
    for(int o=4;o>0;o>>=1){ a+=__shfl_xor_sync(0xffffffffu,a,o); b2+=__shfl_xor_sync(0xffffffffu,b2,o); }
    if(lane==0){ sh[0][0]=a; sh[1][0]=b2; }
  }
  __syncthreads();
  float mean = sh[0][0]*(1.f/DM);
  float var  = fmaxf(sh[1][0]*(1.f/DM) - mean*mean, 0.f);
  float inv  = rsqrtf(var + 1e-5f);
  #pragma unroll
  for(int j=0;j<3;j++){
    int idx = threadIdx.x + j*256;
    float o2 = (v[j]-mean)*inv*w[idx] + bias[idx];
    if(out) out[base+idx] = o2;
    if(pk){
      __nv_bfloat16 hh,ll; split_bf16(o2,hh,ll);
      pk[base+idx] = hh; pk[(size_t)planeN + base+idx] = ll;
    }
  }
}

__global__ void conv_silu_kernel(const float* __restrict__ xz, const float* __restrict__ w,
                                 const float* __restrict__ b, float* __restrict__ xc){
  int i = blockIdx.x*blockDim.x+threadIdx.x;
  if(i>=SS*LL*DI) return;
  int d=i%DI; int l=(i/DI)%LL; int s=i/(DI*LL);
  const float* xin = xz + (size_t)s*LL*2*DI + d;
  float acc = b[d];
  #pragma unroll
  for(int j=0;j<4;j++){
    int ll=l-3+j;
    if(ll>=0) acc = fmaf(w[d*4+j], xin[(size_t)ll*2*DI], acc);
  }
  xc[i] = siluf(acc);
}

__global__ void scan_kernel(const float* __restrict__ xc, const float* __restrict__ delta,
                            const float* __restrict__ xdbl, const float* __restrict__ A_log,
                            const float* __restrict__ Dp, float* __restrict__ y){
  int idx = blockIdx.x*blockDim.x+threadIdx.x;
  if(idx>=SS*DI) return;
  int d = idx%DI; int s = idx/DI;
  float Ar[NS];
  #pragma unroll
  for(int n=0;n<NS;n++) Ar[n] = -__expf(A_log[d*NS+n]);
  float Dv = Dp[d];
  float h[NS];
  #pragma unroll
  for(int n=0;n<NS;n++) h[n]=0.f;
  const float* up = xc    + (size_t)s*LL*DI + d;
  const float* dp = delta + (size_t)s*LL*DI + d;
  const float* xd = xdbl  + (size_t)s*LL*XD;
  float* yp       = y     + (size_t)s*LL*DI + d;
  for(int l=0;l<LL;l++){
    float dl = dp[(size_t)l*DI];
    float u  = up[(size_t)l*DI];
    float du = dl*u;
    const float4* Bm = (const float4*)(xd + (size_t)l*XD + DTR);
    const float4* Cm = (const float4*)(xd + (size_t)l*XD + DTR + NS);
    float out = 0.f;
    #pragma unroll
    for(int q=0;q<4;q++){
      float4 b4 = Bm[q];
      float4 c4 = Cm[q];
      float e;
      e=__expf(dl*Ar[4*q+0]); h[4*q+0]=fmaf(e,h[4*q+0],du*b4.x); out=fmaf(h[4*q+0],c4.x,out);
      e=__expf(dl*Ar[4*q+1]); h[4*q+1]=fmaf(e,h[4*q+1],du*b4.y); out=fmaf(h[4*q+1],c4.y,out);
      e=__expf(dl*Ar[4*q+2]); h[4*q+2]=fmaf(e,h[4*q+2],du*b4.z); out=fmaf(h[4*q+2],c4.z,out);
      e=__expf(dl*Ar[4*q+3]); h[4*q+3]=fmaf(e,h[4*q+3],du*b4.w); out=fmaf(h[4*q+3],c4.w,out);
    }
    yp[(size_t)l*DI] = fmaf(u, Dv, out);
  }
}

// y*silu(z) -> packed split-bf16 (for out_proj GEMM input)
__global__ void gate_pack_kernel(const float* __restrict__ y, const float* __restrict__ xz,
                                 __nv_bfloat16* __restrict__ pk){
  int i=blockIdx.x*blockDim.x+threadIdx.x;
  if(i>=SS*LL*DI) return;
  int r=i/DI, j=i%DI;
  float z = xz[(size_t)r*2*DI + DI + j];
  float v = y[i]*siluf(z);
  __nv_bfloat16 hh,ll; split_bf16(v,hh,ll);
  pk[i]=hh; pk[(size_t)M4*DI + i]=ll;
}

// a*silu(gate) -> packed split-bf16 (for fc2 GEMM input)
__global__ void fc_gate_pack_kernel(const float* __restrict__ big, __nv_bfloat16* __restrict__ pk){
  int i=blockIdx.x*blockDim.x+threadIdx.x;
  if(i>=SS*LL*DI) return;
  int r=i/DI, j=i%DI;
  float a = big[(size_t)r*2*DI + j];
  float b = big[(size_t)r*2*DI + DI + j];
  float v = a*siluf(b);
  __nv_bfloat16 hh,ll; split_bf16(v,hh,ll);
  pk[i]=hh; pk[(size_t)M4*DI + i]=ll;
}

__global__ void combine_kernel(const float* __restrict__ lnx, const float* __restrict__ resA,
                               float* __restrict__ h, float* __restrict__ res){
  int i=blockIdx.x*blockDim.x+threadIdx.x;
  if(i>=BB*LL*DM) return;
  int d=i%DM; int l=(i/DM)%LL; int b=i/(DM*LL);
  size_t f = ((size_t)(b*LL+l))*DM+d;
  size_t r = ((size_t)((2+b)*LL+(LL-1-l)))*DM+d;
  h[i]   = lnx[f]+lnx[r];
  res[i] = resA[f]+resA[r];
}

__global__ void mean_kernel(const float* __restrict__ fin, float* __restrict__ out){
  int i=blockIdx.x*blockDim.x+threadIdx.x;
  if(i>=BB*DM) return;
  int b=i/DM, j=i%DM;
  float s=0.f;
  for(int l=0;l<LL;l++) s += fin[((size_t)(b*LL+l))*DM+j];
  out[i] = s*(1.f/LL);
}

// weight split-pack: fp32 [n] -> hi plane [n], lo plane [n]
__global__ void wpack_kernel(const float* __restrict__ src, __nv_bfloat16* __restrict__ dst, int n){
  int i=blockIdx.x*blockDim.x+threadIdx.x;
  if(i>=n) return;
  __nv_bfloat16 hh,ll; split_bf16(src[i],hh,ll);
  dst[i]=hh; dst[(size_t)n+i]=ll;
}

// ---------------- HMMA (mma.sync bf16, split 3-pass) GEMM ----------------
// C[M,N] = A[M,K] * B[N,K]^T, A/B given as split-bf16 planes (hi, lo).
// M = gridDim.y*128 (exact), N = gridDim.x*128 (exact), K % 16 == 0.
__device__ __forceinline__ uint32_t smem_u32(const void* p){
  uint32_t a;
  asm("{ .reg .u64 t; cvta.to.shared.u64 t, %1; cvt.u32.u64 %0, t; }" : "=r"(a) : "l"(p));
  return a;
}
#define LDSM4(r, addr) \
  asm volatile("ldmatrix.sync.aligned.m8n8.x4.shared.b16 {%0,%1,%2,%3}, [%4];" \
    : "=r"((r)[0]),"=r"((r)[1]),"=r"((r)[2]),"=r"((r)[3]) : "r"(addr))
#define MMA16(d, a, b0, b1) \
  asm volatile("mma.sync.aligned.m16n8k16.row.col.f32.bf16.bf16.f32 " \
    "{%0,%1,%2,%3}, {%4,%5,%6,%7}, {%8,%9}, {%0,%1,%2,%3};" \
    : "+f"((d)[0]),"+f"((d)[1]),"+f"((d)[2]),"+f"((d)[3]) \
    : "r"((a)[0]),"r"((a)[1]),"r"((a)[2]),"r"((a)[3]), "r"(b0),"r"(b1))
#define CPA16(dst,src) asm volatile("cp.async.cg.shared.global [%0], [%1], 16;" :: "r"(dst), "l"(src))
#define CPCOMMIT() asm volatile("cp.async.commit_group;" ::: "memory")
#define CPWAIT2()  asm volatile("cp.async.wait_group 2;" ::: "memory")

#define HM_STAGES 4
#define HM_STAGE_BYTES 24576          // 4 planes x 128 rows x 48B
#define HM_SMEM (HM_STAGES*HM_STAGE_BYTES)

__global__ void __launch_bounds__(256) mm_hmma(
    int K, int N,
    const __nv_bfloat16* __restrict__ Ap,
    const __nv_bfloat16* __restrict__ Bp,
    float* __restrict__ C)
{
  extern __shared__ __align__(128) char smem_[];
  const int tid = threadIdx.x, wid = tid>>5, lane = tid&31;
  const int bm = blockIdx.y, bn = blockIdx.x;
  const size_t aplane = (size_t)gridDim.y*128*K;
  const size_t bplane = (size_t)N*K;
  uint32_t sbase = smem_u32(smem_);

  // loaders: thread t -> row t/2, 16B half t&1, in all 4 planes
  const int lrow = tid>>1, lhalf = tid&1;
  const __nv_bfloat16* gA = Ap + (size_t)(bm*128 + lrow)*K + lhalf*8;
  const __nv_bfloat16* gB = Bp + (size_t)(bn*128 + lrow)*K + lhalf*8;
  const uint32_t sdst = sbase + (uint32_t)lrow*48 + (uint32_t)lhalf*16;

  const int T = K>>4;
  // ldmatrix per-thread offsets (relative to stage base)
  const int warp_m = wid>>1, warp_n = wid&1;
  const int lq = lane&15, lh2 = lane>>4;
  uint32_t aoff[2], boff[4];
  #pragma unroll
  for(int mi=0;mi<2;mi++) aoff[mi] = (uint32_t)((warp_m*32+mi*16+lq)*48 + lh2*16);
  #pragma unroll
  for(int j=0;j<4;j++)    boff[j]  = (uint32_t)((warp_n*64+j*16+lq)*48 + lh2*16);

  float acc[2][8][4];
  #pragma unroll
  for(int mi=0;mi<2;mi++)
    #pragma unroll
    for(int f=0;f<8;f++)
      #pragma unroll
      for(int q=0;q<4;q++) acc[mi][f][q]=0.f;

  // prologue: prefetch 3 stages
  #pragma unroll
  for(int t=0;t<3;t++){
    uint32_t d = sdst + (uint32_t)t*HM_STAGE_BYTES;
    const __nv_bfloat16* a = gA + t*16;
    const __nv_bfloat16* b = gB + t*16;
    CPA16(d,         a);
    CPA16(d+6144,    a + aplane);
    CPA16(d+12288,   b);
    CPA16(d+18432,   b + bplane);
    CPCOMMIT();
  }

  for(int t=0;t<T;t++){
    CPWAIT2();
    __syncthreads();
    uint32_t st_ = sbase + (uint32_t)(t & (HM_STAGES-1))*HM_STAGE_BYTES;
    uint32_t ah[2][4], al[2][4], bh[4][4], bl[4][4];
    #pragma unroll
    for(int mi=0;mi<2;mi++){
      LDSM4(ah[mi], st_ + aoff[mi]);
      LDSM4(al[mi], st_ + 6144u + aoff[mi]);
    }
    #pragma unroll
    for(int j=0;j<4;j++){
      LDSM4(bh[j], st_ + 12288u + boff[j]);
      LDSM4(bl[j], st_ + 18432u + boff[j]);
    }
    #pragma unroll
    for(int mi=0;mi<2;mi++){
      #pragma unroll
      for(int f=0;f<8;f++){
        const int j=f>>1, sel=f&1;
        MMA16(acc[mi][f], ah[mi], bh[j][sel], bh[j][sel+2]);
        MMA16(acc[mi][f], ah[mi], bl[j][sel], bl[j][sel+2]);
        MMA16(acc[mi][f], al[mi], bh[j][sel], bh[j][sel+2]);
      }
    }
    __syncthreads();
    int tn = t+3;
    if(tn < T){
      uint32_t d = sdst + (uint32_t)(tn & (HM_STAGES-1))*HM_STAGE_BYTES;
      const __nv_bfloat16* a = gA + tn*16;
      const __nv_bfloat16* b = gB + tn*16;
      CPA16(d,         a);
      CPA16(d+6144,    a + aplane);
      CPA16(d+12288,   b);
      CPA16(d+18432,   b + bplane);
    }
    CPCOMMIT();   // commit (possibly empty) to keep group accounting uniform
  }

  // epilogue
  const int tr = lane>>2, tc = (lane&3)*2;
  const int row0 = bm*128 + warp_m*32;
  const int col0 = bn*128 + warp_n*64;
  #pragma unroll
  for(int mi=0;mi<2;mi++){
    #pragma unroll
    for(int f=0;f<8;f++){
      float* c0 = C + (size_t)(row0+mi*16+tr)*N + col0 + f*8 + tc;
      float2 v0; v0.x=acc[mi][f][0]; v0.y=acc[mi][f][1];
      float2 v1; v1.x=acc[mi][f][2]; v1.y=acc[mi][f][3];
      *(float2*)c0 = v0;
      *(float2*)(c0 + 8*(size_t)N) = v1;
    }
  }
}

// ---------------- fallback FFMA GEMM (small shapes) ----------------
template<int BM,int BN,int TM,int TN,int BK>
__global__ void __launch_bounds__(256) gemm_nt(
    int M,int N,int K,int lda,
    const float* __restrict__ A, const float* __restrict__ Bw,
    float* __restrict__ C, const float* __restrict__ bias, int act)
{
  __shared__ float As[BK][BM];
  __shared__ float Bs[BK][BN];
  const int t  = threadIdx.x;
  const int bm = blockIdx.y*BM, bn = blockIdx.x*BN;
  const int TCOL = BN/TN;
  const int tx = t % TCOL, ty = t / TCOL;
  const int KQ = BK/4;
  float acc[TM][TN];
  #pragma unroll
  for(int i=0;i<TM;i++)
    #pragma unroll
    for(int j=0;j<TN;j++) acc[i][j]=0.f;

  for(int k0=0;k0<K;k0+=BK){
    for(int i=t;i<BM*KQ;i+=256){
      int row = i/KQ, kq = (i%KQ)*4;
      float4 v = *(const float4*)(A + (size_t)(bm+row)*lda + k0 + kq);
      As[kq][row]=v.x; As[kq+1][row]=v.y; As[kq+2][row]=v.z; As[kq+3][row]=v.w;
    }
    for(int i=t;i<BN*KQ;i+=256){
      int row = i/KQ, kq = (i%KQ)*4;
      int gn = bn+row;
      float4 v = make_float4(0.f,0.f,0.f,0.f);
      if(gn<N) v = *(const float4*)(Bw + (size_t)gn*K + k0 + kq);
      Bs[kq][row]=v.x; Bs[kq+1][row]=v.y; Bs[kq+2][row]=v.z; Bs[kq+3][row]=v.w;
    }
    __syncthreads();
    #pragma unroll
    for(int kk=0;kk<BK;kk++){
      float a[TM], b[TN];
      #pragma unroll
      for(int i=0;i<TM;i++) a[i]=As[kk][ty*TM+i];
      #pragma unroll
      for(int j=0;j<TN;j++) b[j]=Bs[kk][tx*TN+j];
      #pragma unroll
      for(int i=0;i<TM;i++)
        #pragma unroll
        for(int j=0;j<TN;j++) acc[i][j] = fmaf(a[i],b[j],acc[i][j]);
    }
    __syncthreads();
  }
  #pragma unroll
  for(int i=0;i<TM;i++){
    int gm = bm + ty*TM + i;
    #pragma unroll
    for(int j=0;j<TN;j++){
      int gn = bn + tx*TN + j;
      if(gn<N){
        float c = acc[i][j];
        if(bias) c += bias[gn];
        if(act==1) c = (c>20.f)? c : log1pf(__expf(c));
        C[(size_t)gm*N + gn] = c;
      }
    }
  }
}

// ---------------- launcher ----------------
extern "C" void kernel_launch(void* const* d_in, const int* in_sizes, int n_in,
                              void* d_out, int out_size){
  const int*   ids    = (const int*)  d_in[0];
  const float* emb    = (const float*)d_in[1];
  const float* norm_w = (const float*)d_in[2];
  const float* norm_b = (const float*)d_in[3];
  const float* in_proj= (const float*)d_in[4];
  const float* conv_w = (const float*)d_in[5];
  const float* conv_b = (const float*)d_in[6];
  const float* x_proj = (const float*)d_in[7];
  const float* dt_w   = (const float*)d_in[8];
  const float* dt_b   = (const float*)d_in[9];
  const float* A_log  = (const float*)d_in[10];
  const float* Dw     = (const float*)d_in[11];
  const float* out_proj=(const float*)d_in[12];
  const float* norm2_w= (const float*)d_in[13];
  const float* norm2_b= (const float*)d_in[14];
  const float* fc1    = (const float*)d_in[15];
  const float* fc2    = (const float*)d_in[16];
  const float* normf_w= (const float*)d_in[17];
  const float* normf_b= (const float*)d_in[18];
  float* out = (float*)d_out;

  float *p_h,*p_res,*p_resA,*p_x,*p_xz,*p_xc,*p_xdbl,*p_delta,*p_y,*p_bo,*p_fin;
  __nv_bfloat16 *pa768,*pa1536,*pw_in,*pw_fc1,*pw_out,*pw_fc2;
  cudaGetSymbolAddress((void**)&p_h,    g_h);
  cudaGetSymbolAddress((void**)&p_res,  g_res);
  cudaGetSymbolAddress((void**)&p_resA, g_resA);
  cudaGetSymbolAddress((void**)&p_x,    g_x);
  cudaGetSymbolAddress((void**)&p_xz,   g_xz);
  cudaGetSymbolAddress((void**)&p_xc,   g_xc);
  cudaGetSymbolAddress((void**)&p_xdbl, g_xdbl);
  cudaGetSymbolAddress((void**)&p_delta,g_delta);
  cudaGetSymbolAddress((void**)&p_y,    g_y);
  cudaGetSymbolAddress((void**)&p_bo,   g_bo);
  cudaGetSymbolAddress((void**)&p_fin,  g_fin);
  cudaGetSymbolAddress((void**)&pa768,  g_pa768);
  cudaGetSymbolAddress((void**)&pa1536, g_pa1536);
  cudaGetSymbolAddress((void**)&pw_in,  g_pw_in);
  cudaGetSymbolAddress((void**)&pw_fc1, g_pw_fc1);
  cudaGetSymbolAddress((void**)&pw_out, g_pw_out);
  cudaGetSymbolAddress((void**)&pw_fc2, g_pw_fc2);

  cudaFuncSetAttribute(mm_hmma, cudaFuncAttributeMaxDynamicSharedMemorySize, HM_SMEM);

  const int TP=256;
  embed_kernel<<<(BB*LL*DM+TP-1)/TP,TP>>>(ids, emb, p_h);

  // pack all weights into split-bf16 planes
  for(int li=0; li<NLAYER; li++){
    wpack_kernel<<<(2*DI*DM+TP-1)/TP,TP>>>(in_proj + (size_t)li*2*DI*DM, pw_in  + (size_t)li*2*(2*DI)*DM, 2*DI*DM);
    wpack_kernel<<<(2*DI*DM+TP-1)/TP,TP>>>(fc1     + (size_t)li*2*DI*DM, pw_fc1 + (size_t)li*2*(2*DI)*DM, 2*DI*DM);
    wpack_kernel<<<(DM*DI+TP-1)/TP,TP>>>(out_proj + (size_t)li*DM*DI, pw_out + (size_t)li*2*DM*DI, DM*DI);
    wpack_kernel<<<(DM*DI+TP-1)/TP,TP>>>(fc2      + (size_t)li*DM*DI, pw_fc2 + (size_t)li*2*DM*DI, DM*DI);
  }

  for(int li=0; li<NLAYER; li++){
    const float* nw = norm_w  + (size_t)li*DM;
    const float* nb = norm_b  + (size_t)li*DM;
    const float* cw = conv_w  + (size_t)li*DI*4;
    const float* cb = conv_b  + (size_t)li*DI;
    const float* xp = x_proj  + (size_t)li*XD*DI;
    const float* dw = dt_w    + (size_t)li*DI*DTR;
    const float* db = dt_b    + (size_t)li*DI;
    const float* al = A_log   + (size_t)li*DI*NS;
    const float* Dl = Dw      + (size_t)li*DI;
    const float* n2w= norm2_w + (size_t)li*DM;
    const float* n2b= norm2_b + (size_t)li*DM;
    const __nv_bfloat16* wIn = pw_in  + (size_t)li*2*(2*DI)*DM;
    const __nv_bfloat16* wF1 = pw_fc1 + (size_t)li*2*(2*DI)*DM;
    const __nv_bfloat16* wOu = pw_out + (size_t)li*2*DM*DI;
    const __nv_bfloat16* wF2 = pw_fc2 + (size_t)li*2*DM*DI;

    augment_kernel<<<(BB*LL*DM+TP-1)/TP,TP>>>(p_h, p_res, p_resA, li>0);
    // x = LN(res) -> packed split-bf16 (feeds in_proj GEMM only)
    ln_kernel<<<M4,256>>>(p_resA, nullptr, nullptr, nullptr, pa768, M4*DM, nw, nb);

    // xz = x @ in_proj^T  (HMMA)
    { dim3 g(2*DI/128, M4/128); mm_hmma<<<g,256,HM_SMEM>>>(DM, 2*DI, pa768, wIn, p_xz); }

    conv_silu_kernel<<<(SS*LL*DI+TP-1)/TP,TP>>>(p_xz, cw, cb, p_xc);

    // x_dbl = xc @ x_proj^T  (FFMA; N=80 small)
    { dim3 g((XD+15)/16, M4/128); gemm_nt<128,16,8,1,16><<<g,256>>>(M4, XD, DI, DI, p_xc, xp, p_xdbl, nullptr, 0); }
    // delta = softplus(dt @ dt_w^T + dt_b)  (K=48 small)
    { dim3 g(DI/128, M4/128); gemm_nt<128,128,8,8,16><<<g,256>>>(M4, DI, DTR, XD, p_xdbl, dw, p_delta, db, 1); }

    scan_kernel<<<(SS*DI+TP-1)/TP,TP>>>(p_xc, p_delta, p_xdbl, al, Dl, p_y);
    // y*silu(z) -> packed (feeds out_proj only)
    gate_pack_kernel<<<(SS*LL*DI+TP-1)/TP,TP>>>(p_y, p_xz, pa1536);

    // mixer_out = y @ out_proj^T (HMMA)
    { dim3 g(DM/128, M4/128); mm_hmma<<<g,256,HM_SMEM>>>(DI, DM, pa1536, wOu, p_bo); }

    // res += mixer_out ; x2 = LN(res, norm2) -> packed (feeds fc1 only)
    ln_kernel<<<M4,256>>>(p_bo, p_resA, p_resA, nullptr, pa768, M4*DM, n2w, n2b);

    // fc1 (HMMA)
    { dim3 g(2*DI/128, M4/128); mm_hmma<<<g,256,HM_SMEM>>>(DM, 2*DI, pa768, wF1, p_xz); }

    // gated MLP -> packed (feeds fc2 only)
    fc_gate_pack_kernel<<<(SS*LL*DI+TP-1)/TP,TP>>>(p_xz, pa1536);

    // fc2 (HMMA)
    { dim3 g(DM/128, M4/128); mm_hmma<<<g,256,HM_SMEM>>>(DI, DM, pa1536, wF2, p_bo); }

    // final norm on block outputs (fp32 out), then fwd+reverse(bwd) combine
    ln_kernel<<<M4,256>>>(p_bo, nullptr, nullptr, p_x, nullptr, 0, normf_w, normf_b);
    combine_kernel<<<(BB*LL*DM+TP-1)/TP,TP>>>(p_x, p_resA, p_h, p_res);
  }

  ln_kernel<<<BB*LL,256>>>(p_h, p_res, nullptr, p_fin, nullptr, 0, normf_w, normf_b);
  mean_kernel<<<(BB*DM+TP-1)/TP,TP>>>(p_fin, out);
}

// round 6
// speedup vs baseline: 1.7143x; 1.0717x over previous
#include <cuda_runtime.h>
#include <cuda_bf16.h>
#include <math.h>
#include <stdint.h>

#define BB 2
#define LL 1024
#define DM 768
#define NLAYER 2
#define DI 1536
#define NS 16
#define DTR 48
#define XD 80           // DTR + 2*NS
#define SS 4            // augmented batch: [fwd b0, fwd b1, bwd b0, bwd b1]
#define M4 (SS*LL)      // 4096 GEMM rows

// ---------------- scratch (static __device__, no allocation) ----------------
__device__ __align__(128) float g_h[BB*LL*DM];
__device__ __align__(128) float g_res[BB*LL*DM];
__device__ __align__(128) float g_resA[SS*LL*DM];
__device__ __align__(128) float g_x[SS*LL*DM];
__device__ __align__(128) float g_xz[SS*LL*2*DI];
__device__ __align__(128) float g_xc[SS*LL*DI];
__device__ __align__(128) float g_xdbl[SS*LL*XD];
__device__ __align__(128) float g_delta[SS*LL*DI];
__device__ __align__(128) float g_y[SS*LL*DI];
__device__ __align__(128) float g_bo[SS*LL*DM];
__device__ __align__(128) float g_fin[BB*LL*DM];

// split-bf16 activation/weight planes: [hi plane][lo plane], row-major
__device__ __align__(128) __nv_bfloat16 g_pa768 [2*M4*DM];
__device__ __align__(128) __nv_bfloat16 g_pa1536[2*M4*DI];
__device__ __align__(128) __nv_bfloat16 g_pw_in [NLAYER*2*(2*DI)*DM];
__device__ __align__(128) __nv_bfloat16 g_pw_fc1[NLAYER*2*(2*DI)*DM];
__device__ __align__(128) __nv_bfloat16 g_pw_out[NLAYER*2*DM*DI];
__device__ __align__(128) __nv_bfloat16 g_pw_fc2[NLAYER*2*DM*DI];

__device__ __forceinline__ float siluf(float x){ return x/(1.f+__expf(-x)); }

__device__ __forceinline__ void split_bf16(float v, __nv_bfloat16& h, __nv_bfloat16& l){
  h = __float2bfloat16(v);
  l = __float2bfloat16(v - __bfloat162float(h));
}

// ---------------- elementwise kernels ----------------
__global__ void embed_kernel(const int* __restrict__ ids, const float* __restrict__ emb,
                             float* __restrict__ out){
  int i = blockIdx.x*blockDim.x+threadIdx.x;
  if(i>=BB*LL*DM) return;
  int d=i%DM; int t=i/DM;
  out[i] = emb[(size_t)ids[t]*DM + d];
}

// Fused: v = h (+res); resA[fwd]=resA[bwd-mirror]=v; LN(v) -> split-bf16 planes
// written to both fwd row and mirrored bwd row (LN is reversal-invariant).
__global__ void aug_ln_pack_kernel(const float* __restrict__ h, const float* __restrict__ res,
                                   float* __restrict__ resA, __nv_bfloat16* __restrict__ pk,
                                   const float* __restrict__ w, const float* __restrict__ bias,
                                   int use_res){
  int r = blockIdx.x;              // 0 .. BB*LL-1
  int b = r / LL, l = r % LL;
  size_t fbase = (size_t)(b*LL + l)*DM;
  size_t rbase = (size_t)((2+b)*LL + (LL-1-l))*DM;
  float v[3]; float s=0.f,s2=0.f;
  #pragma unroll
  for(int j=0;j<3;j++){
    int idx = threadIdx.x + j*256;
    float t = h[fbase+idx];       // note: h/res are [BB*LL*DM], fwd rows coincide
    if(use_res) t += res[fbase+idx];
    v[j]=t; s+=t; s2+=t*t;
    resA[fbase+idx]=t; resA[rbase+idx]=t;
  }
  #pragma unroll
  for(int o=16;o>0;o>>=1){ s+=__shfl_xor_sync(0xffffffffu,s,o); s2+=__shfl_xor_sync(0xffffffffu,s2,o); }
  __shared__ float sh[2][8];
  int wid=threadIdx.x>>5, lane=threadIdx.x&31;
  if(lane==0){ sh[0][wid]=s; sh[1][wid]=s2; }
  __syncthreads();
  if(threadIdx.x<32){
    float a = lane<8? sh[0][lane]:0.f;
    float b2= lane<8? sh[1][lane]:0.f;
    #pragma unroll
    for(int o=4;o>0;o>>=1){ a+=__shfl_xor_sync(0xffffffffu,a,o); b2+=__shfl_xor_sync(0xffffffffu,b2,o); }
    if(lane==0){ sh[0][0]=a; sh[1][0]=b2; }
  }
  __syncthreads();
  float mean = sh[0][0]*(1.f/DM);
  float var  = fmaxf(sh[1][0]*(1.f/DM) - mean*mean, 0.f);
  float inv  = rsqrtf(var + 1e-5f);
  #pragma unroll
  for(int j=0;j<3;j++){
    int idx = threadIdx.x + j*256;
    float o2 = (v[j]-mean)*inv*w[idx] + bias[idx];
    __nv_bfloat16 hh,ll; split_bf16(o2,hh,ll);
    pk[fbase+idx]=hh; pk[(size_t)M4*DM + fbase+idx]=ll;
    pk[rbase+idx]=hh; pk[(size_t)M4*DM + rbase+idx]=ll;
  }
}

// Row LayerNorm over DM=768. Optional pre-add, optional fp32 sum writeback,
// optional fp32 out, optional packed split-bf16 out (planeN = plane elem count).
__global__ void ln_kernel(const float* __restrict__ in, const float* __restrict__ addin,
                          float* __restrict__ sumout, float* __restrict__ out,
                          __nv_bfloat16* __restrict__ pk, int planeN,
                          const float* __restrict__ w, const float* __restrict__ bias){
  int r = blockIdx.x;
  size_t base = (size_t)r*DM;
  float v[3]; float s=0.f,s2=0.f;
  #pragma unroll
  for(int j=0;j<3;j++){
    int idx = threadIdx.x + j*256;
    float t = in[base+idx];
    if(addin) t += addin[base+idx];
    v[j]=t; s+=t; s2+=t*t;
  }
  if(sumout){
    #pragma unroll
    for(int j=0;j<3;j++) sumout[base+threadIdx.x+j*256]=v[j];
  }
  #pragma unroll
  for(int o=16;o>0;o>>=1){ s+=__shfl_xor_sync(0xffffffffu,s,o); s2+=__shfl_xor_sync(0xffffffffu,s2,o); }
  __shared__ float sh[2][8];
  int wid=threadIdx.x>>5, lane=threadIdx.x&31;
  if(lane==0){ sh[0][wid]=s; sh[1][wid]=s2; }
  __syncthreads();
  if(threadIdx.x<32){
    float a = lane<8? sh[0][lane]:0.f;
    float b2= lane<8? sh[1][lane]:0.f;
    #pragma unroll
    for(int o=4;o>0;o>>=1){ a+=__shfl_xor_sync(0xffffffffu,a,o); b2+=__shfl_xor_sync(0xffffffffu,b2,o); }
    if(lane==0){ sh[0][0]=a; sh[1][0]=b2; }
  }
  __syncthreads();
  float mean = sh[0][0]*(1.f/DM);
  float var  = fmaxf(sh[1][0]*(1.f/DM) - mean*mean, 0.f);
  float inv  = rsqrtf(var + 1e-5f);
  #pragma unroll
  for(int j=0;j<3;j++){
    int idx = threadIdx.x + j*256;
    float o2 = (v[j]-mean)*inv*w[idx] + bias[idx];
    if(out) out[base+idx] = o2;
    if(pk){
      __nv_bfloat16 hh,ll; split_bf16(o2,hh,ll);
      pk[base+idx] = hh; pk[(size_t)planeN + base+idx] = ll;
    }
  }
}

__global__ void conv_silu_kernel(const float* __restrict__ xz, const float* __restrict__ w,
                                 const float* __restrict__ b, float* __restrict__ xc){
  int i = blockIdx.x*blockDim.x+threadIdx.x;
  if(i>=SS*LL*DI) return;
  int d=i%DI; int l=(i/DI)%LL; int s=i/(DI*LL);
  const float* xin = xz + (size_t)s*LL*2*DI + d;
  float acc = b[d];
  #pragma unroll
  for(int j=0;j<4;j++){
    int ll=l-3+j;
    if(ll>=0) acc = fmaf(w[d*4+j], xin[(size_t)ll*2*DI], acc);
  }
  xc[i] = siluf(acc);
}

// selective scan; fast path exploits A_n = (n+1)*A_1 structure (guarded at runtime)
__global__ void scan_kernel(const float* __restrict__ xc, const float* __restrict__ delta,
                            const float* __restrict__ xdbl, const float* __restrict__ A_log,
                            const float* __restrict__ Dp, float* __restrict__ y){
  int idx = blockIdx.x*blockDim.x+threadIdx.x;
  if(idx>=SS*DI) return;
  int d = idx%DI; int s = idx/DI;
  float Ar[NS];
  #pragma unroll
  for(int n=0;n<NS;n++) Ar[n] = -__expf(A_log[d*NS+n]);
  float a1 = Ar[0];
  bool fast = true;
  #pragma unroll
  for(int n=0;n<NS;n++){
    float expect = (n+1)*a1;
    if(fabsf(Ar[n]-expect) > 1e-5f*fabsf(expect)) fast = false;
  }
  float Dv = Dp[d];
  float h[NS];
  #pragma unroll
  for(int n=0;n<NS;n++) h[n]=0.f;
  const float* up = xc    + (size_t)s*LL*DI + d;
  const float* dp = delta + (size_t)s*LL*DI + d;
  const float* xd = xdbl  + (size_t)s*LL*XD;
  float* yp       = y     + (size_t)s*LL*DI + d;

  if(fast){
    // prefetch l=0
    float dl = dp[0], u = up[0];
    float4 B4[4], C4[4];
    #pragma unroll
    for(int q=0;q<4;q++){
      B4[q] = ((const float4*)(xd + DTR))[q];
      C4[q] = ((const float4*)(xd + DTR + NS))[q];
    }
    for(int l=0;l<LL;l++){
      float cdl=dl, cu=u;
      float4 cB[4], cC[4];
      #pragma unroll
      for(int q=0;q<4;q++){ cB[q]=B4[q]; cC[q]=C4[q]; }
      if(l+1<LL){
        dl = dp[(size_t)(l+1)*DI];
        u  = up[(size_t)(l+1)*DI];
        #pragma unroll
        for(int q=0;q<4;q++){
          B4[q] = ((const float4*)(xd + (size_t)(l+1)*XD + DTR))[q];
          C4[q] = ((const float4*)(xd + (size_t)(l+1)*XD + DTR + NS))[q];
        }
      }
      float du = cdl*cu;
      float e1 = __expf(cdl*a1);
      float e2 = e1*e1, e3 = e2*e1, e4 = e2*e2;
      float f1 = e4, f2 = e4*e4, f3 = f2*e4;
      float dA[NS];
      dA[0]=e1;    dA[1]=e2;    dA[2]=e3;    dA[3]=e4;
      dA[4]=f1*e1; dA[5]=f1*e2; dA[6]=f1*e3; dA[7]=f1*e4;
      dA[8]=f2*e1; dA[9]=f2*e2; dA[10]=f2*e3; dA[11]=f2*e4;
      dA[12]=f3*e1; dA[13]=f3*e2; dA[14]=f3*e3; dA[15]=f3*e4;
      float out = 0.f;
      #pragma unroll
      for(int q=0;q<4;q++){
        h[4*q+0]=fmaf(dA[4*q+0],h[4*q+0],du*cB[q].x); out=fmaf(h[4*q+0],cC[q].x,out);
        h[4*q+1]=fmaf(dA[4*q+1],h[4*q+1],du*cB[q].y); out=fmaf(h[4*q+1],cC[q].y,out);
        h[4*q+2]=fmaf(dA[4*q+2],h[4*q+2],du*cB[q].z); out=fmaf(h[4*q+2],cC[q].z,out);
        h[4*q+3]=fmaf(dA[4*q+3],h[4*q+3],du*cB[q].w); out=fmaf(h[4*q+3],cC[q].w,out);
      }
      yp[(size_t)l*DI] = fmaf(cu, Dv, out);
    }
  } else {
    for(int l=0;l<LL;l++){
      float dl = dp[(size_t)l*DI];
      float u  = up[(size_t)l*DI];
      float du = dl*u;
      const float4* Bm = (const float4*)(xd + (size_t)l*XD + DTR);
      const float4* Cm = (const float4*)(xd + (size_t)l*XD + DTR + NS);
      float out = 0.f;
      #pragma unroll
      for(int q=0;q<4;q++){
        float4 b4 = Bm[q];
        float4 c4 = Cm[q];
        float e;
        e=__expf(dl*Ar[4*q+0]); h[4*q+0]=fmaf(e,h[4*q+0],du*b4.x); out=fmaf(h[4*q+0],c4.x,out);
        e=__expf(dl*Ar[4*q+1]); h[4*q+1]=fmaf(e,h[4*q+1],du*b4.y); out=fmaf(h[4*q+1],c4.y,out);
        e=__expf(dl*Ar[4*q+2]); h[4*q+2]=fmaf(e,h[4*q+2],du*b4.z); out=fmaf(h[4*q+2],c4.z,out);
        e=__expf(dl*Ar[4*q+3]); h[4*q+3]=fmaf(e,h[4*q+3],du*b4.w); out=fmaf(h[4*q+3],c4.w,out);
      }
      yp[(size_t)l*DI] = fmaf(u, Dv, out);
    }
  }
}

// y*silu(z) -> packed split-bf16 (for out_proj GEMM input)
__global__ void gate_pack_kernel(const float* __restrict__ y, const float* __restrict__ xz,
                                 __nv_bfloat16* __restrict__ pk){
  int i=blockIdx.x*blockDim.x+threadIdx.x;
  if(i>=SS*LL*DI) return;
  int r=i/DI, j=i%DI;
  float z = xz[(size_t)r*2*DI + DI + j];
  float v = y[i]*siluf(z);
  __nv_bfloat16 hh,ll; split_bf16(v,hh,ll);
  pk[i]=hh; pk[(size_t)M4*DI + i]=ll;
}

// a*silu(gate) -> packed split-bf16 (for fc2 GEMM input)
__global__ void fc_gate_pack_kernel(const float* __restrict__ big, __nv_bfloat16* __restrict__ pk){
  int i=blockIdx.x*blockDim.x+threadIdx.x;
  if(i>=SS*LL*DI) return;
  int r=i/DI, j=i%DI;
  float a = big[(size_t)r*2*DI + j];
  float b = big[(size_t)r*2*DI + DI + j];
  float v = a*siluf(b);
  __nv_bfloat16 hh,ll; split_bf16(v,hh,ll);
  pk[i]=hh; pk[(size_t)M4*DI + i]=ll;
}

__global__ void combine_kernel(const float* __restrict__ lnx, const float* __restrict__ resA,
                               float* __restrict__ h, float* __restrict__ res){
  int i=blockIdx.x*blockDim.x+threadIdx.x;
  if(i>=BB*LL*DM) return;
  int d=i%DM; int l=(i/DM)%LL; int b=i/(DM*LL);
  size_t f = ((size_t)(b*LL+l))*DM+d;
  size_t r = ((size_t)((2+b)*LL+(LL-1-l)))*DM+d;
  h[i]   = lnx[f]+lnx[r];
  res[i] = resA[f]+resA[r];
}

__global__ void mean_kernel(const float* __restrict__ fin, float* __restrict__ out){
  int i=blockIdx.x*blockDim.x+threadIdx.x;
  if(i>=BB*DM) return;
  int b=i/DM, j=i%DM;
  float s=0.f;
  for(int l=0;l<LL;l++) s += fin[((size_t)(b*LL+l))*DM+j];
  out[i] = s*(1.f/LL);
}

// weight split-pack: fp32 [n] -> hi plane [n], lo plane [n]
__global__ void wpack_kernel(const float* __restrict__ src, __nv_bfloat16* __restrict__ dst, int n){
  int i=blockIdx.x*blockDim.x+threadIdx.x;
  if(i>=n) return;
  __nv_bfloat16 hh,ll; split_bf16(src[i],hh,ll);
  dst[i]=hh; dst[(size_t)n+i]=ll;
}

// ---------------- HMMA (mma.sync bf16, split 3-pass) GEMM ----------------
// C[M,N] = A[M,K] * B[N,K]^T, A/B given as split-bf16 planes (hi, lo).
// M = gridDim.y*128 (exact), N = gridDim.x*128 (exact), K % 16 == 0.
// Conflict-free smem: 16B chunk of (row r, half c) at (r>>3)*256 + (r&7)*16 + c*128.
__device__ __forceinline__ uint32_t smem_u32(const void* p){
  uint32_t a;
  asm("{ .reg .u64 t; cvta.to.shared.u64 t, %1; cvt.u32.u64 %0, t; }" : "=r"(a) : "l"(p));
  return a;
}
#define LDSM4(r, addr) \
  asm volatile("ldmatrix.sync.aligned.m8n8.x4.shared.b16 {%0,%1,%2,%3}, [%4];" \
    : "=r"((r)[0]),"=r"((r)[1]),"=r"((r)[2]),"=r"((r)[3]) : "r"(addr))
#define MMA16(d, a, b0, b1) \
  asm volatile("mma.sync.aligned.m16n8k16.row.col.f32.bf16.bf16.f32 " \
    "{%0,%1,%2,%3}, {%4,%5,%6,%7}, {%8,%9}, {%0,%1,%2,%3};" \
    : "+f"((d)[0]),"+f"((d)[1]),"+f"((d)[2]),"+f"((d)[3]) \
    : "r"((a)[0]),"r"((a)[1]),"r"((a)[2]),"r"((a)[3]), "r"(b0),"r"(b1))
#define CPA16(dst,src) asm volatile("cp.async.cg.shared.global [%0], [%1], 16;" :: "r"(dst), "l"(src))
#define CPCOMMIT() asm volatile("cp.async.commit_group;" ::: "memory")
#define CPWAIT2()  asm volatile("cp.async.wait_group 2;" ::: "memory")

#define HM_STAGES 4
#define HM_PLANE_BYTES 4096           // 128 rows x 32B, swizzled groups of 8 rows (256B)
#define HM_STAGE_BYTES 16384          // 4 planes (A_hi, A_lo, B_hi, B_lo)
#define HM_SMEM (HM_STAGES*HM_STAGE_BYTES)

__device__ __forceinline__ uint32_t hm_off(int row, int half){
  return (uint32_t)((row>>3)*256 + (row&7)*16 + half*128);
}

__global__ void __launch_bounds__(256) mm_hmma(
    int K, int N,
    const __nv_bfloat16* __restrict__ Ap,
    const __nv_bfloat16* __restrict__ Bp,
    float* __restrict__ C)
{
  extern __shared__ __align__(128) char smem_[];
  const int tid = threadIdx.x, wid = tid>>5, lane = tid&31;
  const int bm = blockIdx.y, bn = blockIdx.x;
  const size_t aplane = (size_t)gridDim.y*128*K;
  const size_t bplane = (size_t)N*K;
  uint32_t sbase = smem_u32(smem_);

  // loaders: thread t -> row t/2, 16B half t&1, in all 4 planes
  const int lrow = tid>>1, lhalf = tid&1;
  const __nv_bfloat16* gA = Ap + (size_t)(bm*128 + lrow)*K + lhalf*8;
  const __nv_bfloat16* gB = Bp + (size_t)(bn*128 + lrow)*K + lhalf*8;
  const uint32_t sdst = sbase + hm_off(lrow, lhalf);

  const int T = K>>4;
  // ldmatrix per-thread offsets (relative to stage plane base)
  const int warp_m = wid>>1, warp_n = wid&1;
  const int lq = lane&15, lh2 = lane>>4;
  uint32_t aoff[2], boff[4];
  #pragma unroll
  for(int mi=0;mi<2;mi++) aoff[mi] = hm_off(warp_m*32+mi*16+lq, lh2);
  #pragma unroll
  for(int j=0;j<4;j++)    boff[j]  = hm_off(warp_n*64+j*16+lq, lh2);

  float acc[2][8][4];
  #pragma unroll
  for(int mi=0;mi<2;mi++)
    #pragma unroll
    for(int f=0;f<8;f++)
      #pragma unroll
      for(int q=0;q<4;q++) acc[mi][f][q]=0.f;

  // prologue: prefetch 3 stages
  #pragma unroll
  for(int t=0;t<3;t++){
    uint32_t d = sdst + (uint32_t)t*HM_STAGE_BYTES;
    const __nv_bfloat16* a = gA + t*16;
    const __nv_bfloat16* b = gB + t*16;
    CPA16(d,                     a);
    CPA16(d +   HM_PLANE_BYTES,  a + aplane);
    CPA16(d + 2*HM_PLANE_BYTES,  b);
    CPA16(d + 3*HM_PLANE_BYTES,  b + bplane);
    CPCOMMIT();
  }

  for(int t=0;t<T;t++){
    CPWAIT2();
    __syncthreads();
    uint32_t st_ = sbase + (uint32_t)(t & (HM_STAGES-1))*HM_STAGE_BYTES;
    uint32_t ah[2][4], al[2][4], bh[4][4], bl[4][4];
    #pragma unroll
    for(int mi=0;mi<2;mi++){
      LDSM4(ah[mi], st_ + aoff[mi]);
      LDSM4(al[mi], st_ + HM_PLANE_BYTES + aoff[mi]);
    }
    #pragma unroll
    for(int j=0;j<4;j++){
      LDSM4(bh[j], st_ + 2*HM_PLANE_BYTES + boff[j]);
      LDSM4(bl[j], st_ + 3*HM_PLANE_BYTES + boff[j]);
    }
    #pragma unroll
    for(int mi=0;mi<2;mi++){
      #pragma unroll
      for(int f=0;f<8;f++){
        const int j=f>>1, sel=f&1;
        MMA16(acc[mi][f], ah[mi], bh[j][sel], bh[j][sel+2]);
        MMA16(acc[mi][f], ah[mi], bl[j][sel], bl[j][sel+2]);
        MMA16(acc[mi][f], al[mi], bh[j][sel], bh[j][sel+2]);
      }
    }
    __syncthreads();
    int tn = t+3;
    if(tn < T){
      uint32_t d = sdst + (uint32_t)(tn & (HM_STAGES-1))*HM_STAGE_BYTES;
      const __nv_bfloat16* a = gA + tn*16;
      const __nv_bfloat16* b = gB + tn*16;
      CPA16(d,                     a);
      CPA16(d +   HM_PLANE_BYTES,  a + aplane);
      CPA16(d + 2*HM_PLANE_BYTES,  b);
      CPA16(d + 3*HM_PLANE_BYTES,  b + bplane);
    }
    CPCOMMIT();   // commit (possibly empty) to keep group accounting uniform
  }

  // epilogue
  const int tr = lane>>2, tc = (lane&3)*2;
  const int row0 = bm*128 + warp_m*32;
  const int col0 = bn*128 + warp_n*64;
  #pragma unroll
  for(int mi=0;mi<2;mi++){
    #pragma unroll
    for(int f=0;f<8;f++){
      float* c0 = C + (size_t)(row0+mi*16+tr)*N + col0 + f*8 + tc;
      float2 v0; v0.x=acc[mi][f][0]; v0.y=acc[mi][f][1];
      float2 v1; v1.x=acc[mi][f][2]; v1.y=acc[mi][f][3];
      *(float2*)c0 = v0;
      *(float2*)(c0 + 8*(size_t)N) = v1;
    }
  }
}

// ---------------- fallback FFMA GEMM (small shapes) ----------------
template<int BM,int BN,int TM,int TN,int BK>
__global__ void __launch_bounds__(256) gemm_nt(
    int M,int N,int K,int lda,
    const float* __restrict__ A, const float* __restrict__ Bw,
    float* __restrict__ C, const float* __restrict__ bias, int act)
{
  __shared__ float As[BK][BM];
  __shared__ float Bs[BK][BN];
  const int t  = threadIdx.x;
  const int bm = blockIdx.y*BM, bn = blockIdx.x*BN;
  const int TCOL = BN/TN;
  const int tx = t % TCOL, ty = t / TCOL;
  const int KQ = BK/4;
  float acc[TM][TN];
  #pragma unroll
  for(int i=0;i<TM;i++)
    #pragma unroll
    for(int j=0;j<TN;j++) acc[i][j]=0.f;

  for(int k0=0;k0<K;k0+=BK){
    for(int i=t;i<BM*KQ;i+=256){
      int row = i/KQ, kq = (i%KQ)*4;
      float4 v = *(const float4*)(A + (size_t)(bm+row)*lda + k0 + kq);
      As[kq][row]=v.x; As[kq+1][row]=v.y; As[kq+2][row]=v.z; As[kq+3][row]=v.w;
    }
    for(int i=t;i<BN*KQ;i+=256){
      int row = i/KQ, kq = (i%KQ)*4;
      int gn = bn+row;
      float4 v = make_float4(0.f,0.f,0.f,0.f);
      if(gn<N) v = *(const float4*)(Bw + (size_t)gn*K + k0 + kq);
      Bs[kq][row]=v.x; Bs[kq+1][row]=v.y; Bs[kq+2][row]=v.z; Bs[kq+3][row]=v.w;
    }
    __syncthreads();
    #pragma unroll
    for(int kk=0;kk<BK;kk++){
      float a[TM], b[TN];
      #pragma unroll
      for(int i=0;i<TM;i++) a[i]=As[kk][ty*TM+i];
      #pragma unroll
      for(int j=0;j<TN;j++) b[j]=Bs[kk][tx*TN+j];
      #pragma unroll
      for(int i=0;i<TM;i++)
        #pragma unroll
        for(int j=0;j<TN;j++) acc[i][j] = fmaf(a[i],b[j],acc[i][j]);
    }
    __syncthreads();
  }
  #pragma unroll
  for(int i=0;i<TM;i++){
    int gm = bm + ty*TM + i;
    #pragma unroll
    for(int j=0;j<TN;j++){
      int gn = bn + tx*TN + j;
      if(gn<N){
        float c = acc[i][j];
        if(bias) c += bias[gn];
        if(act==1) c = (c>20.f)? c : log1pf(__expf(c));
        C[(size_t)gm*N + gn] = c;
      }
    }
  }
}

// ---------------- launcher ----------------
extern "C" void kernel_launch(void* const* d_in, const int* in_sizes, int n_in,
                              void* d_out, int out_size){
  const int*   ids    = (const int*)  d_in[0];
  const float* emb    = (const float*)d_in[1];
  const float* norm_w = (const float*)d_in[2];
  const float* norm_b = (const float*)d_in[3];
  const float* in_proj= (const float*)d_in[4];
  const float* conv_w = (const float*)d_in[5];
  const float* conv_b = (const float*)d_in[6];
  const float* x_proj = (const float*)d_in[7];
  const float* dt_w   = (const float*)d_in[8];
  const float* dt_b   = (const float*)d_in[9];
  const float* A_log  = (const float*)d_in[10];
  const float* Dw     = (const float*)d_in[11];
  const float* out_proj=(const float*)d_in[12];
  const float* norm2_w= (const float*)d_in[13];
  const float* norm2_b= (const float*)d_in[14];
  const float* fc1    = (const float*)d_in[15];
  const float* fc2    = (const float*)d_in[16];
  const float* normf_w= (const float*)d_in[17];
  const float* normf_b= (const float*)d_in[18];
  float* out = (float*)d_out;

  float *p_h,*p_res,*p_resA,*p_x,*p_xz,*p_xc,*p_xdbl,*p_delta,*p_y,*p_bo,*p_fin;
  __nv_bfloat16 *pa768,*pa1536,*pw_in,*pw_fc1,*pw_out,*pw_fc2;
  cudaGetSymbolAddress((void**)&p_h,    g_h);
  cudaGetSymbolAddress((void**)&p_res,  g_res);
  cudaGetSymbolAddress((void**)&p_resA, g_resA);
  cudaGetSymbolAddress((void**)&p_x,    g_x);
  cudaGetSymbolAddress((void**)&p_xz,   g_xz);
  cudaGetSymbolAddress((void**)&p_xc,   g_xc);
  cudaGetSymbolAddress((void**)&p_xdbl, g_xdbl);
  cudaGetSymbolAddress((void**)&p_delta,g_delta);
  cudaGetSymbolAddress((void**)&p_y,    g_y);
  cudaGetSymbolAddress((void**)&p_bo,   g_bo);
  cudaGetSymbolAddress((void**)&p_fin,  g_fin);
  cudaGetSymbolAddress((void**)&pa768,  g_pa768);
  cudaGetSymbolAddress((void**)&pa1536, g_pa1536);
  cudaGetSymbolAddress((void**)&pw_in,  g_pw_in);
  cudaGetSymbolAddress((void**)&pw_fc1, g_pw_fc1);
  cudaGetSymbolAddress((void**)&pw_out, g_pw_out);
  cudaGetSymbolAddress((void**)&pw_fc2, g_pw_fc2);

  cudaFuncSetAttribute(mm_hmma, cudaFuncAttributeMaxDynamicSharedMemorySize, HM_SMEM);

  const int TP=256;
  embed_kernel<<<(BB*LL*DM+TP-1)/TP,TP>>>(ids, emb, p_h);

  // pack all weights into split-bf16 planes
  for(int li=0; li<NLAYER; li++){
    wpack_kernel<<<(2*DI*DM+TP-1)/TP,TP>>>(in_proj + (size_t)li*2*DI*DM, pw_in  + (size_t)li*2*(2*DI)*DM, 2*DI*DM);
    wpack_kernel<<<(2*DI*DM+TP-1)/TP,TP>>>(fc1     + (size_t)li*2*DI*DM, pw_fc1 + (size_t)li*2*(2*DI)*DM, 2*DI*DM);
    wpack_kernel<<<(DM*DI+TP-1)/TP,TP>>>(out_proj + (size_t)li*DM*DI, pw_out + (size_t)li*2*DM*DI, DM*DI);
    wpack_kernel<<<(DM*DI+TP-1)/TP,TP>>>(fc2      + (size_t)li*DM*DI, pw_fc2 + (size_t)li*2*DM*DI, DM*DI);
  }

  for(int li=0; li<NLAYER; li++){
    const float* nw = norm_w  + (size_t)li*DM;
    const float* nb = norm_b  + (size_t)li*DM;
    const float* cw = conv_w  + (size_t)li*DI*4;
    const float* cb = conv_b  + (size_t)li*DI;
    const float* xp = x_proj  + (size_t)li*XD*DI;
    const float* dw = dt_w    + (size_t)li*DI*DTR;
    const float* db = dt_b    + (size_t)li*DI;
    const float* al = A_log   + (size_t)li*DI*NS;
    const float* Dl = Dw      + (size_t)li*DI;
    const float* n2w= norm2_w + (size_t)li*DM;
    const float* n2b= norm2_b + (size_t)li*DM;
    const __nv_bfloat16* wIn = pw_in  + (size_t)li*2*(2*DI)*DM;
    const __nv_bfloat16* wF1 = pw_fc1 + (size_t)li*2*(2*DI)*DM;
    const __nv_bfloat16* wOu = pw_out + (size_t)li*2*DM*DI;
    const __nv_bfloat16* wF2 = pw_fc2 + (size_t)li*2*DM*DI;

    // fused: res accumulate + augmented copy + LN + split-pack
    aug_ln_pack_kernel<<<BB*LL,256>>>(p_h, p_res, p_resA, pa768, nw, nb, li>0);

    // xz = x @ in_proj^T  (HMMA)
    { dim3 g(2*DI/128, M4/128); mm_hmma<<<g,256,HM_SMEM>>>(DM, 2*DI, pa768, wIn, p_xz); }

    conv_silu_kernel<<<(SS*LL*DI+TP-1)/TP,TP>>>(p_xz, cw, cb, p_xc);

    // x_dbl = xc @ x_proj^T  (FFMA; N=80 small)
    { dim3 g((XD+15)/16, M4/128); gemm_nt<128,16,8,1,16><<<g,256>>>(M4, XD, DI, DI, p_xc, xp, p_xdbl, nullptr, 0); }
    // delta = softplus(dt @ dt_w^T + dt_b)  (K=48 small)
    { dim3 g(DI/128, M4/128); gemm_nt<128,128,8,8,16><<<g,256>>>(M4, DI, DTR, XD, p_xdbl, dw, p_delta, db, 1); }

    scan_kernel<<<(SS*DI+TP-1)/TP,TP>>>(p_xc, p_delta, p_xdbl, al, Dl, p_y);
    // y*silu(z) -> packed (feeds out_proj only)
    gate_pack_kernel<<<(SS*LL*DI+TP-1)/TP,TP>>>(p_y, p_xz, pa1536);

    // mixer_out = y @ out_proj^T (HMMA)
    { dim3 g(DM/128, M4/128); mm_hmma<<<g,256,HM_SMEM>>>(DI, DM, pa1536, wOu, p_bo); }

    // res += mixer_out ; x2 = LN(res, norm2) -> packed (feeds fc1 only)
    ln_kernel<<<M4,256>>>(p_bo, p_resA, p_resA, nullptr, pa768, M4*DM, n2w, n2b);

    // fc1 (HMMA)
    { dim3 g(2*DI/128, M4/128); mm_hmma<<<g,256,HM_SMEM>>>(DM, 2*DI, pa768, wF1, p_xz); }

    // gated MLP -> packed (feeds fc2 only)
    fc_gate_pack_kernel<<<(SS*LL*DI+TP-1)/TP,TP>>>(p_xz, pa1536);

    // fc2 (HMMA)
    { dim3 g(DM/128, M4/128); mm_hmma<<<g,256,HM_SMEM>>>(DI, DM, pa1536, wF2, p_bo); }

    // final norm on block outputs (fp32 out), then fwd+reverse(bwd) combine
    ln_kernel<<<M4,256>>>(p_bo, nullptr, nullptr, p_x, nullptr, 0, normf_w, normf_b);
    combine_kernel<<<(BB*LL*DM+TP-1)/TP,TP>>>(p_x, p_resA, p_h, p_res);
  }

  ln_kernel<<<BB*LL,256>>>(p_h, p_res, nullptr, p_fin, nullptr, 0, normf_w, normf_b);
  mean_kernel<<<(BB*DM+TP-1)/TP,TP>>>(p_fin, out);
}

// round 7
// speedup vs baseline: 1.7286x; 1.0083x over previous
#include <cuda_runtime.h>
#include <cuda_bf16.h>
#include <math.h>
#include <stdint.h>

#define BB 2
#define LL 1024
#define DM 768
#define NLAYER 2
#define DI 1536
#define NS 16
#define DTR 48
#define XD 80           // DTR + 2*NS
#define XDP 128         // padded x_dbl width
#define SS 4            // augmented batch: [fwd b0, fwd b1, bwd b0, bwd b1]
#define M4 (SS*LL)      // 4096 GEMM rows

// ---------------- scratch (static __device__, no allocation) ----------------
__device__ __align__(128) float g_h[BB*LL*DM];
__device__ __align__(128) float g_res[BB*LL*DM];
__device__ __align__(128) float g_resA[SS*LL*DM];
__device__ __align__(128) float g_x[SS*LL*DM];
__device__ __align__(128) float g_xz[SS*LL*2*DI];
__device__ __align__(128) float g_xc[SS*LL*DI];
__device__ __align__(128) float g_xdbl[M4*XDP];
__device__ __align__(128) float g_delta[SS*LL*DI];
__device__ __align__(128) float g_y[SS*LL*DI];
__device__ __align__(128) float g_bo[SS*LL*DM];
__device__ __align__(128) float g_fin[BB*LL*DM];

// split-bf16 activation/weight planes: [hi plane][lo plane], row-major
__device__ __align__(128) __nv_bfloat16 g_pa768 [2*M4*DM];
__device__ __align__(128) __nv_bfloat16 g_pa1536[2*M4*DI];
__device__ __align__(128) __nv_bfloat16 g_pw_in [NLAYER*2*(2*DI)*DM];
__device__ __align__(128) __nv_bfloat16 g_pw_fc1[NLAYER*2*(2*DI)*DM];
__device__ __align__(128) __nv_bfloat16 g_pw_out[NLAYER*2*DM*DI];
__device__ __align__(128) __nv_bfloat16 g_pw_fc2[NLAYER*2*DM*DI];
__device__ __align__(128) __nv_bfloat16 g_pw_xp [NLAYER*2*XDP*DI];

__device__ __forceinline__ float siluf(float x){ return x/(1.f+__expf(-x)); }

__device__ __forceinline__ void split_bf16(float v, __nv_bfloat16& h, __nv_bfloat16& l){
  h = __float2bfloat16(v);
  l = __float2bfloat16(v - __bfloat162float(h));
}

// ---------------- elementwise kernels ----------------
__global__ void embed_kernel(const int* __restrict__ ids, const float* __restrict__ emb,
                             float* __restrict__ out){
  int i = blockIdx.x*blockDim.x+threadIdx.x;
  if(i>=BB*LL*DM) return;
  int d=i%DM; int t=i/DM;
  out[i] = emb[(size_t)ids[t]*DM + d];
}

// Fused: v = h (+res); resA[fwd]=resA[bwd-mirror]=v; LN(v) -> split-bf16 planes
__global__ void aug_ln_pack_kernel(const float* __restrict__ h, const float* __restrict__ res,
                                   float* __restrict__ resA, __nv_bfloat16* __restrict__ pk,
                                   const float* __restrict__ w, const float* __restrict__ bias,
                                   int use_res){
  int r = blockIdx.x;              // 0 .. BB*LL-1
  int b = r / LL, l = r % LL;
  size_t fbase = (size_t)(b*LL + l)*DM;
  size_t rbase = (size_t)((2+b)*LL + (LL-1-l))*DM;
  float v[3]; float s=0.f,s2=0.f;
  #pragma unroll
  for(int j=0;j<3;j++){
    int idx = threadIdx.x + j*256;
    float t = h[fbase+idx];
    if(use_res) t += res[fbase+idx];
    v[j]=t; s+=t; s2+=t*t;
    resA[fbase+idx]=t; resA[rbase+idx]=t;
  }
  #pragma unroll
  for(int o=16;o>0;o>>=1){ s+=__shfl_xor_sync(0xffffffffu,s,o); s2+=__shfl_xor_sync(0xffffffffu,s2,o); }
  __shared__ float sh[2][8];
  int wid=threadIdx.x>>5, lane=threadIdx.x&31;
  if(lane==0){ sh[0][wid]=s; sh[1][wid]=s2; }
  __syncthreads();
  if(threadIdx.x<32){
    float a = lane<8? sh[0][lane]:0.f;
    float b2= lane<8? sh[1][lane]:0.f;
    #pragma unroll
    for(int o=4;o>0;o>>=1){ a+=__shfl_xor_sync(0xffffffffu,a,o); b2+=__shfl_xor_sync(0xffffffffu,b2,o); }
    if(lane==0){ sh[0][0]=a; sh[1][0]=b2; }
  }
  __syncthreads();
  float mean = sh[0][0]*(1.f/DM);
  float var  = fmaxf(sh[1][0]*(1.f/DM) - mean*mean, 0.f);
  float inv  = rsqrtf(var + 1e-5f);
  #pragma unroll
  for(int j=0;j<3;j++){
    int idx = threadIdx.x + j*256;
    float o2 = (v[j]-mean)*inv*w[idx] + bias[idx];
    __nv_bfloat16 hh,ll; split_bf16(o2,hh,ll);
    pk[fbase+idx]=hh; pk[(size_t)M4*DM + fbase+idx]=ll;
    pk[rbase+idx]=hh; pk[(size_t)M4*DM + rbase+idx]=ll;
  }
}

// Row LayerNorm over DM=768. Optional pre-add, optional fp32 sum writeback,
// optional fp32 out, optional packed split-bf16 out.
__global__ void ln_kernel(const float* __restrict__ in, const float* __restrict__ addin,
                          float* __restrict__ sumout, float* __restrict__ out,
                          __nv_bfloat16* __restrict__ pk, int planeN,
                          const float* __restrict__ w, const float* __restrict__ bias){
  int r = blockIdx.x;
  size_t base = (size_t)r*DM;
  float v[3]; float s=0.f,s2=0.f;
  #pragma unroll
  for(int j=0;j<3;j++){
    int idx = threadIdx.x + j*256;
    float t = in[base+idx];
    if(addin) t += addin[base+idx];
    v[j]=t; s+=t; s2+=t*t;
  }
  if(sumout){
    #pragma unroll
    for(int j=0;j<3;j++) sumout[base+threadIdx.x+j*256]=v[j];
  }
  #pragma unroll
  for(int o=16;o>0;o>>=1){ s+=__shfl_xor_sync(0xffffffffu,s,o); s2+=__shfl_xor_sync(0xffffffffu,s2,o); }
  __shared__ float sh[2][8];
  int wid=threadIdx.x>>5, lane=threadIdx.x&31;
  if(lane==0){ sh[0][wid]=s; sh[1][wid]=s2; }
  __syncthreads();
  if(threadIdx.x<32){
    float a = lane<8? sh[0][lane]:0.f;
    float b2= lane<8? sh[1][lane]:0.f;
    #pragma unroll
    for(int o=4;o>0;o>>=1){ a+=__shfl_xor_sync(0xffffffffu,a,o); b2+=__shfl_xor_sync(0xffffffffu,b2,o); }
    if(lane==0){ sh[0][0]=a; sh[1][0]=b2; }
  }
  __syncthreads();
  float mean = sh[0][0]*(1.f/DM);
  float var  = fmaxf(sh[1][0]*(1.f/DM) - mean*mean, 0.f);
  float inv  = rsqrtf(var + 1e-5f);
  #pragma unroll
  for(int j=0;j<3;j++){
    int idx = threadIdx.x + j*256;
    float o2 = (v[j]-mean)*inv*w[idx] + bias[idx];
    if(out) out[base+idx] = o2;
    if(pk){
      __nv_bfloat16 hh,ll; split_bf16(o2,hh,ll);
      pk[base+idx] = hh; pk[(size_t)planeN + base+idx] = ll;
    }
  }
}

// depthwise causal conv + silu; writes fp32 xc AND split-bf16 planes (x_proj GEMM input)
__global__ void conv_silu_pack_kernel(const float* __restrict__ xz, const float* __restrict__ w,
                                      const float* __restrict__ b, float* __restrict__ xc,
                                      __nv_bfloat16* __restrict__ pk){
  int i = blockIdx.x*blockDim.x+threadIdx.x;
  if(i>=SS*LL*DI) return;
  int d=i%DI; int l=(i/DI)%LL; int s=i/(DI*LL);
  const float* xin = xz + (size_t)s*LL*2*DI + d;
  float acc = b[d];
  #pragma unroll
  for(int j=0;j<4;j++){
    int ll=l-3+j;
    if(ll>=0) acc = fmaf(w[d*4+j], xin[(size_t)ll*2*DI], acc);
  }
  float v = siluf(acc);
  xc[i] = v;
  __nv_bfloat16 hh,ll2; split_bf16(v,hh,ll2);
  pk[i]=hh; pk[(size_t)M4*DI + i]=ll2;
}

// selective scan: 4 threads per (s,d) channel, 4 states each; quad shfl reduce.
// fast path exploits A_n = (n+1)*A_1 structure (guarded at runtime).
__global__ void scan_kernel(const float* __restrict__ xc, const float* __restrict__ delta,
                            const float* __restrict__ xd_all, const float* __restrict__ A_log,
                            const float* __restrict__ Dp, float* __restrict__ y){
  int t = blockIdx.x*blockDim.x + threadIdx.x;
  if(t >= SS*DI*4) return;
  const int q = t & 3;
  const int ch = t >> 2;
  const int d = ch % DI, s = ch / DI;
  float Ar[4];
  #pragma unroll
  for(int j=0;j<4;j++) Ar[j] = -__expf(A_log[d*NS + 4*q + j]);
  float a1 = -__expf(A_log[d*NS]);
  bool okl = true;
  #pragma unroll
  for(int j=0;j<4;j++){
    float expect = (4*q+j+1)*a1;
    okl = okl && (fabsf(Ar[j]-expect) <= 1e-5f*fabsf(expect));
  }
  unsigned bal = __ballot_sync(0xffffffffu, okl);
  int qb = (threadIdx.x & 31) & ~3;
  bool fast = (((bal >> qb) & 0xFu) == 0xFu);
  float Dv = Dp[d];
  float h0=0.f,h1=0.f,h2=0.f,h3=0.f;
  const float* up = xc    + (size_t)s*LL*DI + d;
  const float* dp = delta + (size_t)s*LL*DI + d;
  const float* xd = xd_all + (size_t)s*LL*XDP;
  float* yp       = y     + (size_t)s*LL*DI + d;

  float dl = dp[0], u = up[0];
  float4 B4 = *(const float4*)(xd + DTR + 4*q);
  float4 C4 = *(const float4*)(xd + DTR + NS + 4*q);
  for(int l=0;l<LL;l++){
    float cdl=dl, cu=u; float4 cB=B4, cC=C4;
    if(l+1<LL){
      const float* nx = xd + (size_t)(l+1)*XDP;
      dl = dp[(size_t)(l+1)*DI]; u = up[(size_t)(l+1)*DI];
      B4 = *(const float4*)(nx + DTR + 4*q);
      C4 = *(const float4*)(nx + DTR + NS + 4*q);
    }
    float du = cdl*cu;
    float dA0,dA1,dA2,dA3;
    if(fast){
      float e1 = __expf(cdl*a1);
      float e2=e1*e1, e3=e2*e1, e4=e2*e2;
      float base;
      if(q==0) base=1.f; else if(q==1) base=e4; else if(q==2) base=e4*e4; else base=e4*e4*e4;
      dA0=base*e1; dA1=base*e2; dA2=base*e3; dA3=base*e4;
    } else {
      dA0=__expf(cdl*Ar[0]); dA1=__expf(cdl*Ar[1]);
      dA2=__expf(cdl*Ar[2]); dA3=__expf(cdl*Ar[3]);
    }
    h0=fmaf(dA0,h0,du*cB.x); h1=fmaf(dA1,h1,du*cB.y);
    h2=fmaf(dA2,h2,du*cB.z); h3=fmaf(dA3,h3,du*cB.w);
    float part = fmaf(h0,cC.x, fmaf(h1,cC.y, fmaf(h2,cC.z, h3*cC.w)));
    part += __shfl_xor_sync(0xffffffffu, part, 1);
    part += __shfl_xor_sync(0xffffffffu, part, 2);
    if(q==0) yp[(size_t)l*DI] = fmaf(cu, Dv, part);
  }
}

// y*silu(z) -> packed split-bf16 (for out_proj GEMM input)
__global__ void gate_pack_kernel(const float* __restrict__ y, const float* __restrict__ xz,
                                 __nv_bfloat16* __restrict__ pk){
  int i=blockIdx.x*blockDim.x+threadIdx.x;
  if(i>=SS*LL*DI) return;
  int r=i/DI, j=i%DI;
  float z = xz[(size_t)r*2*DI + DI + j];
  float v = y[i]*siluf(z);
  __nv_bfloat16 hh,ll; split_bf16(v,hh,ll);
  pk[i]=hh; pk[(size_t)M4*DI + i]=ll;
}

// a*silu(gate) -> packed split-bf16 (for fc2 GEMM input)
__global__ void fc_gate_pack_kernel(const float* __restrict__ big, __nv_bfloat16* __restrict__ pk){
  int i=blockIdx.x*blockDim.x+threadIdx.x;
  if(i>=SS*LL*DI) return;
  int r=i/DI, j=i%DI;
  float a = big[(size_t)r*2*DI + j];
  float b = big[(size_t)r*2*DI + DI + j];
  float v = a*siluf(b);
  __nv_bfloat16 hh,ll; split_bf16(v,hh,ll);
  pk[i]=hh; pk[(size_t)M4*DI + i]=ll;
}

__global__ void combine_kernel(const float* __restrict__ lnx, const float* __restrict__ resA,
                               float* __restrict__ h, float* __restrict__ res){
  int i=blockIdx.x*blockDim.x+threadIdx.x;
  if(i>=BB*LL*DM) return;
  int d=i%DM; int l=(i/DM)%LL; int b=i/(DM*LL);
  size_t f = ((size_t)(b*LL+l))*DM+d;
  size_t r = ((size_t)((2+b)*LL+(LL-1-l)))*DM+d;
  h[i]   = lnx[f]+lnx[r];
  res[i] = resA[f]+resA[r];
}

__global__ void mean_kernel(const float* __restrict__ fin, float* __restrict__ out){
  int i=blockIdx.x*blockDim.x+threadIdx.x;
  if(i>=BB*DM) return;
  int b=i/DM, j=i%DM;
  float s=0.f;
  for(int l=0;l<LL;l++) s += fin[((size_t)(b*LL+l))*DM+j];
  out[i] = s*(1.f/LL);
}

// weight split-pack: fp32 [n] -> hi plane [n], lo plane [n]
__global__ void wpack_kernel(const float* __restrict__ src, __nv_bfloat16* __restrict__ dst, int n){
  int i=blockIdx.x*blockDim.x+threadIdx.x;
  if(i>=n) return;
  __nv_bfloat16 hh,ll; split_bf16(src[i],hh,ll);
  dst[i]=hh; dst[(size_t)n+i]=ll;
}

// x_proj weight: [XD][DI] -> padded [XDP][DI] split planes (rows >= XD are zero)
__global__ void wpack_pad_kernel(const float* __restrict__ src, __nv_bfloat16* __restrict__ dst){
  int i=blockIdx.x*blockDim.x+threadIdx.x;
  if(i>=XDP*DI) return;
  int row=i/DI, col=i%DI;
  float v = (row<XD) ? src[(size_t)row*DI+col] : 0.f;
  __nv_bfloat16 hh,ll; split_bf16(v,hh,ll);
  dst[i]=hh; dst[(size_t)XDP*DI+i]=ll;
}

// ---------------- HMMA (mma.sync bf16, split 3-pass) GEMM ----------------
__device__ __forceinline__ uint32_t smem_u32(const void* p){
  uint32_t a;
  asm("{ .reg .u64 t; cvta.to.shared.u64 t, %1; cvt.u32.u64 %0, t; }" : "=r"(a) : "l"(p));
  return a;
}
#define LDSM4(r, addr) \
  asm volatile("ldmatrix.sync.aligned.m8n8.x4.shared.b16 {%0,%1,%2,%3}, [%4];" \
    : "=r"((r)[0]),"=r"((r)[1]),"=r"((r)[2]),"=r"((r)[3]) : "r"(addr))
#define MMA16(d, a, b0, b1) \
  asm volatile("mma.sync.aligned.m16n8k16.row.col.f32.bf16.bf16.f32 " \
    "{%0,%1,%2,%3}, {%4,%5,%6,%7}, {%8,%9}, {%0,%1,%2,%3};" \
    : "+f"((d)[0]),"+f"((d)[1]),"+f"((d)[2]),"+f"((d)[3]) \
    : "r"((a)[0]),"r"((a)[1]),"r"((a)[2]),"r"((a)[3]), "r"(b0),"r"(b1))
#define CPA16(dst,src) asm volatile("cp.async.cg.shared.global [%0], [%1], 16;" :: "r"(dst), "l"(src))
#define CPCOMMIT() asm volatile("cp.async.commit_group;" ::: "memory")
#define CPWAIT2()  asm volatile("cp.async.wait_group 2;" ::: "memory")

#define HM_STAGES 4
#define HM_PLANE_BYTES 4096
#define HM_STAGE_BYTES 16384
#define HM_SMEM (HM_STAGES*HM_STAGE_BYTES)

__device__ __forceinline__ uint32_t hm_off(int row, int half){
  return (uint32_t)((row>>3)*256 + (row&7)*16 + half*128);
}

__global__ void __launch_bounds__(256) mm_hmma(
    int K, int N,
    const __nv_bfloat16* __restrict__ Ap,
    const __nv_bfloat16* __restrict__ Bp,
    float* __restrict__ C)
{
  extern __shared__ __align__(128) char smem_[];
  const int tid = threadIdx.x, wid = tid>>5, lane = tid&31;
  const int bm = blockIdx.y, bn = blockIdx.x;
  const size_t aplane = (size_t)gridDim.y*128*K;
  const size_t bplane = (size_t)N*K;
  uint32_t sbase = smem_u32(smem_);

  const int lrow = tid>>1, lhalf = tid&1;
  const __nv_bfloat16* gA = Ap + (size_t)(bm*128 + lrow)*K + lhalf*8;
  const __nv_bfloat16* gB = Bp + (size_t)(bn*128 + lrow)*K + lhalf*8;
  const uint32_t sdst = sbase + hm_off(lrow, lhalf);

  const int T = K>>4;
  const int warp_m = wid>>1, warp_n = wid&1;
  const int lq = lane&15, lh2 = lane>>4;
  uint32_t aoff[2], boff[4];
  #pragma unroll
  for(int mi=0;mi<2;mi++) aoff[mi] = hm_off(warp_m*32+mi*16+lq, lh2);
  #pragma unroll
  for(int j=0;j<4;j++)    boff[j]  = hm_off(warp_n*64+j*16+lq, lh2);

  float acc[2][8][4];
  #pragma unroll
  for(int mi=0;mi<2;mi++)
    #pragma unroll
    for(int f=0;f<8;f++)
      #pragma unroll
      for(int q=0;q<4;q++) acc[mi][f][q]=0.f;

  #pragma unroll
  for(int t=0;t<3;t++){
    uint32_t d = sdst + (uint32_t)t*HM_STAGE_BYTES;
    const __nv_bfloat16* a = gA + t*16;
    const __nv_bfloat16* b = gB + t*16;
    CPA16(d,                     a);
    CPA16(d +   HM_PLANE_BYTES,  a + aplane);
    CPA16(d + 2*HM_PLANE_BYTES,  b);
    CPA16(d + 3*HM_PLANE_BYTES,  b + bplane);
    CPCOMMIT();
  }

  for(int t=0;t<T;t++){
    CPWAIT2();
    __syncthreads();
    uint32_t st_ = sbase + (uint32_t)(t & (HM_STAGES-1))*HM_STAGE_BYTES;
    uint32_t ah[2][4], al[2][4], bh[4][4], bl[4][4];
    #pragma unroll
    for(int mi=0;mi<2;mi++){
      LDSM4(ah[mi], st_ + aoff[mi]);
      LDSM4(al[mi], st_ + HM_PLANE_BYTES + aoff[mi]);
    }
    #pragma unroll
    for(int j=0;j<4;j++){
      LDSM4(bh[j], st_ + 2*HM_PLANE_BYTES + boff[j]);
      LDSM4(bl[j], st_ + 3*HM_PLANE_BYTES + boff[j]);
    }
    #pragma unroll
    for(int mi=0;mi<2;mi++){
      #pragma unroll
      for(int f=0;f<8;f++){
        const int j=f>>1, sel=f&1;
        MMA16(acc[mi][f], ah[mi], bh[j][sel], bh[j][sel+2]);
        MMA16(acc[mi][f], ah[mi], bl[j][sel], bl[j][sel+2]);
        MMA16(acc[mi][f], al[mi], bh[j][sel], bh[j][sel+2]);
      }
    }
    // NOTE: no second __syncthreads needed — top-of-iter barrier already
    // guarantees all warps finished reading stage (t+3)&3 (== (t-1)&3).
    int tn = t+3;
    if(tn < T){
      uint32_t d = sdst + (uint32_t)(tn & (HM_STAGES-1))*HM_STAGE_BYTES;
      const __nv_bfloat16* a = gA + tn*16;
      const __nv_bfloat16* b = gB + tn*16;
      CPA16(d,                     a);
      CPA16(d +   HM_PLANE_BYTES,  a + aplane);
      CPA16(d + 2*HM_PLANE_BYTES,  b);
      CPA16(d + 3*HM_PLANE_BYTES,  b + bplane);
    }
    CPCOMMIT();
  }

  const int tr = lane>>2, tc = (lane&3)*2;
  const int row0 = bm*128 + warp_m*32;
  const int col0 = bn*128 + warp_n*64;
  #pragma unroll
  for(int mi=0;mi<2;mi++){
    #pragma unroll
    for(int f=0;f<8;f++){
      float* c0 = C + (size_t)(row0+mi*16+tr)*N + col0 + f*8 + tc;
      float2 v0; v0.x=acc[mi][f][0]; v0.y=acc[mi][f][1];
      float2 v1; v1.x=acc[mi][f][2]; v1.y=acc[mi][f][3];
      *(float2*)c0 = v0;
      *(float2*)(c0 + 8*(size_t)N) = v1;
    }
  }
}

// ---------------- fallback FFMA GEMM (delta: K=48) ----------------
template<int BM,int BN,int TM,int TN,int BK>
__global__ void __launch_bounds__(256) gemm_nt(
    int M,int N,int K,int lda,
    const float* __restrict__ A, const float* __restrict__ Bw,
    float* __restrict__ C, const float* __restrict__ bias, int act)
{
  __shared__ float As[BK][BM];
  __shared__ float Bs[BK][BN];
  const int t  = threadIdx.x;
  const int bm = blockIdx.y*BM, bn = blockIdx.x*BN;
  const int TCOL = BN/TN;
  const int tx = t % TCOL, ty = t / TCOL;
  const int KQ = BK/4;
  float acc[TM][TN];
  #pragma unroll
  for(int i=0;i<TM;i++)
    #pragma unroll
    for(int j=0;j<TN;j++) acc[i][j]=0.f;

  for(int k0=0;k0<K;k0+=BK){
    for(int i=t;i<BM*KQ;i+=256){
      int row = i/KQ, kq = (i%KQ)*4;
      float4 v = *(const float4*)(A + (size_t)(bm+row)*lda + k0 + kq);
      As[kq][row]=v.x; As[kq+1][row]=v.y; As[kq+2][row]=v.z; As[kq+3][row]=v.w;
    }
    for(int i=t;i<BN*KQ;i+=256){
      int row = i/KQ, kq = (i%KQ)*4;
      int gn = bn+row;
      float4 v = make_float4(0.f,0.f,0.f,0.f);
      if(gn<N) v = *(const float4*)(Bw + (size_t)gn*K + k0 + kq);
      Bs[kq][row]=v.x; Bs[kq+1][row]=v.y; Bs[kq+2][row]=v.z; Bs[kq+3][row]=v.w;
    }
    __syncthreads();
    #pragma unroll
    for(int kk=0;kk<BK;kk++){
      float a[TM], b[TN];
      #pragma unroll
      for(int i=0;i<TM;i++) a[i]=As[kk][ty*TM+i];
      #pragma unroll
      for(int j=0;j<TN;j++) b[j]=Bs[kk][tx*TN+j];
      #pragma unroll
      for(int i=0;i<TM;i++)
        #pragma unroll
        for(int j=0;j<TN;j++) acc[i][j] = fmaf(a[i],b[j],acc[i][j]);
    }
    __syncthreads();
  }
  #pragma unroll
  for(int i=0;i<TM;i++){
    int gm = bm + ty*TM + i;
    #pragma unroll
    for(int j=0;j<TN;j++){
      int gn = bn + tx*TN + j;
      if(gn<N){
        float c = acc[i][j];
        if(bias) c += bias[gn];
        if(act==1) c = (c>20.f)? c : log1pf(__expf(c));
        C[(size_t)gm*N + gn] = c;
      }
    }
  }
}

// ---------------- launcher ----------------
extern "C" void kernel_launch(void* const* d_in, const int* in_sizes, int n_in,
                              void* d_out, int out_size){
  const int*   ids    = (const int*)  d_in[0];
  const float* emb    = (const float*)d_in[1];
  const float* norm_w = (const float*)d_in[2];
  const float* norm_b = (const float*)d_in[3];
  const float* in_proj= (const float*)d_in[4];
  const float* conv_w = (const float*)d_in[5];
  const float* conv_b = (const float*)d_in[6];
  const float* x_proj = (const float*)d_in[7];
  const float* dt_w   = (const float*)d_in[8];
  const float* dt_b   = (const float*)d_in[9];
  const float* A_log  = (const float*)d_in[10];
  const float* Dw     = (const float*)d_in[11];
  const float* out_proj=(const float*)d_in[12];
  const float* norm2_w= (const float*)d_in[13];
  const float* norm2_b= (const float*)d_in[14];
  const float* fc1    = (const float*)d_in[15];
  const float* fc2    = (const float*)d_in[16];
  const float* normf_w= (const float*)d_in[17];
  const float* normf_b= (const float*)d_in[18];
  float* out = (float*)d_out;

  float *p_h,*p_res,*p_resA,*p_x,*p_xz,*p_xc,*p_xdbl,*p_delta,*p_y,*p_bo,*p_fin;
  __nv_bfloat16 *pa768,*pa1536,*pw_in,*pw_fc1,*pw_out,*pw_fc2,*pw_xp;
  cudaGetSymbolAddress((void**)&p_h,    g_h);
  cudaGetSymbolAddress((void**)&p_res,  g_res);
  cudaGetSymbolAddress((void**)&p_resA, g_resA);
  cudaGetSymbolAddress((void**)&p_x,    g_x);
  cudaGetSymbolAddress((void**)&p_xz,   g_xz);
  cudaGetSymbolAddress((void**)&p_xc,   g_xc);
  cudaGetSymbolAddress((void**)&p_xdbl, g_xdbl);
  cudaGetSymbolAddress((void**)&p_delta,g_delta);
  cudaGetSymbolAddress((void**)&p_y,    g_y);
  cudaGetSymbolAddress((void**)&p_bo,   g_bo);
  cudaGetSymbolAddress((void**)&p_fin,  g_fin);
  cudaGetSymbolAddress((void**)&pa768,  g_pa768);
  cudaGetSymbolAddress((void**)&pa1536, g_pa1536);
  cudaGetSymbolAddress((void**)&pw_in,  g_pw_in);
  cudaGetSymbolAddress((void**)&pw_fc1, g_pw_fc1);
  cudaGetSymbolAddress((void**)&pw_out, g_pw_out);
  cudaGetSymbolAddress((void**)&pw_fc2, g_pw_fc2);
  cudaGetSymbolAddress((void**)&pw_xp,  g_pw_xp);

  cudaFuncSetAttribute(mm_hmma, cudaFuncAttributeMaxDynamicSharedMemorySize, HM_SMEM);

  const int TP=256;
  // Launch order matters for ncu (-s 5 -c 1): launch #6 must be mm_hmma(in_proj L0).
  embed_kernel<<<(BB*LL*DM+TP-1)/TP,TP>>>(ids, emb, p_h);                                     // 1
  wpack_kernel<<<(2*DI*DM+TP-1)/TP,TP>>>(in_proj, pw_in, 2*DI*DM);                             // 2
  wpack_kernel<<<(DM*DI+TP-1)/TP,TP>>>(out_proj, pw_out, DM*DI);                               // 3
  wpack_kernel<<<(2*DI*DM+TP-1)/TP,TP>>>(fc1, pw_fc1, 2*DI*DM);                                // 4

  for(int li=0; li<NLAYER; li++){
    const float* nw = norm_w  + (size_t)li*DM;
    const float* nb = norm_b  + (size_t)li*DM;
    const float* cw = conv_w  + (size_t)li*DI*4;
    const float* cb = conv_b  + (size_t)li*DI;
    const float* dw = dt_w    + (size_t)li*DI*DTR;
    const float* db = dt_b    + (size_t)li*DI;
    const float* al = A_log   + (size_t)li*DI*NS;
    const float* Dl = Dw      + (size_t)li*DI;
    const float* n2w= norm2_w + (size_t)li*DM;
    const float* n2b= norm2_b + (size_t)li*DM;
    const __nv_bfloat16* wIn = pw_in  + (size_t)li*2*(2*DI)*DM;
    const __nv_bfloat16* wF1 = pw_fc1 + (size_t)li*2*(2*DI)*DM;
    const __nv_bfloat16* wOu = pw_out + (size_t)li*2*DM*DI;
    const __nv_bfloat16* wF2 = pw_fc2 + (size_t)li*2*DM*DI;
    const __nv_bfloat16* wXp = pw_xp  + (size_t)li*2*XDP*DI;

    if(li==1){
      wpack_kernel<<<(2*DI*DM+TP-1)/TP,TP>>>(in_proj + (size_t)1*2*DI*DM, pw_in  + (size_t)1*2*(2*DI)*DM, 2*DI*DM);
      wpack_kernel<<<(DM*DI+TP-1)/TP,TP>>>(out_proj + (size_t)1*DM*DI, pw_out + (size_t)1*2*DM*DI, DM*DI);
      wpack_kernel<<<(2*DI*DM+TP-1)/TP,TP>>>(fc1     + (size_t)1*2*DI*DM, pw_fc1 + (size_t)1*2*(2*DI)*DM, 2*DI*DM);
      wpack_kernel<<<(DM*DI+TP-1)/TP,TP>>>(fc2      + (size_t)1*DM*DI, pw_fc2 + (size_t)1*2*DM*DI, DM*DI);
      wpack_pad_kernel<<<(XDP*DI+TP-1)/TP,TP>>>(x_proj + (size_t)1*XD*DI, pw_xp + (size_t)1*2*XDP*DI);
    }

    // fused: res accumulate + augmented copy + LN + split-pack                               // 5 (li=0)
    aug_ln_pack_kernel<<<BB*LL,256>>>(p_h, p_res, p_resA, pa768, nw, nb, li>0);

    // xz = x @ in_proj^T  (HMMA)                                                             // 6 (li=0)
    { dim3 g(2*DI/128, M4/128); mm_hmma<<<g,256,HM_SMEM>>>(DM, 2*DI, pa768, wIn, p_xz); }

    if(li==0){
      wpack_kernel<<<(DM*DI+TP-1)/TP,TP>>>(fc2, pw_fc2, DM*DI);
      wpack_pad_kernel<<<(XDP*DI+TP-1)/TP,TP>>>(x_proj, pw_xp);
    }

    // conv + silu + split-pack xc
    conv_silu_pack_kernel<<<(SS*LL*DI+TP-1)/TP,TP>>>(p_xz, cw, cb, p_xc, pa1536);

    // x_dbl(padded) = xc @ x_proj_pad^T  (HMMA, N=128)
    { dim3 g(1, M4/128); mm_hmma<<<g,256,HM_SMEM>>>(DI, XDP, pa1536, wXp, p_xdbl); }

    // delta = softplus(dt @ dt_w^T + dt_b)  (K=48, lda=XDP)
    { dim3 g(DI/128, M4/128); gemm_nt<128,128,8,8,16><<<g,256>>>(M4, DI, DTR, XDP, p_xdbl, dw, p_delta, db, 1); }

    // selective scan (quad-split)
    scan_kernel<<<(SS*DI*4+127)/128,128>>>(p_xc, p_delta, p_xdbl, al, Dl, p_y);
    // y*silu(z) -> packed (feeds out_proj only)
    gate_pack_kernel<<<(SS*LL*DI+TP-1)/TP,TP>>>(p_y, p_xz, pa1536);

    // mixer_out = y @ out_proj^T (HMMA)
    { dim3 g(DM/128, M4/128); mm_hmma<<<g,256,HM_SMEM>>>(DI, DM, pa1536, wOu, p_bo); }

    // res += mixer_out ; x2 = LN(res, norm2) -> packed (feeds fc1 only)
    ln_kernel<<<M4,256>>>(p_bo, p_resA, p_resA, nullptr, pa768, M4*DM, n2w, n2b);

    // fc1 (HMMA)
    { dim3 g(2*DI/128, M4/128); mm_hmma<<<g,256,HM_SMEM>>>(DM, 2*DI, pa768, wF1, p_xz); }

    // gated MLP -> packed (feeds fc2 only)
    fc_gate_pack_kernel<<<(SS*LL*DI+TP-1)/TP,TP>>>(p_xz, pa1536);

    // fc2 (HMMA)
    { dim3 g(DM/128, M4/128); mm_hmma<<<g,256,HM_SMEM>>>(DI, DM, pa1536, wF2, p_bo); }

    // final norm on block outputs (fp32 out), then fwd+reverse(bwd) combine
    ln_kernel<<<M4,256>>>(p_bo, nullptr, nullptr, p_x, nullptr, 0, normf_w, normf_b);
    combine_kernel<<<(BB*LL*DM+TP-1)/TP,TP>>>(p_x, p_resA, p_h, p_res);
  }

  ln_kernel<<<BB*LL,256>>>(p_h, p_res, nullptr, p_fin, nullptr, 0, normf_w, normf_b);
  mean_kernel<<<(BB*DM+TP-1)/TP,TP>>>(p_fin, out);
}

// round 8
// speedup vs baseline: 1.8022x; 1.0426x over previous
#include <cuda_runtime.h>
#include <cuda_bf16.h>
#include <math.h>
#include <stdint.h>

#define BB 2
#define LL 1024
#define DM 768
#define NLAYER 2
#define DI 1536
#define NS 16
#define DTR 48
#define XD 80           // DTR + 2*NS
#define XDP 128         // padded x_dbl width
#define SS 4            // augmented batch: [fwd b0, fwd b1, bwd b0, bwd b1]
#define M4 (SS*LL)      // 4096 rows (augmented)
#define M2 (2*LL)       // 2048 rows (fwd only, in_proj GEMM)

// ---------------- scratch (static __device__, no allocation) ----------------
__device__ __align__(128) float g_h[BB*LL*DM];
__device__ __align__(128) float g_res[BB*LL*DM];
__device__ __align__(128) float g_resA[SS*LL*DM];
__device__ __align__(128) float g_x[SS*LL*DM];
__device__ __align__(128) float g_xz[M2*2*DI];          // fwd only
__device__ __align__(128) float g_xc[SS*LL*DI];
__device__ __align__(128) float g_xdbl[M4*XDP];
__device__ __align__(128) float g_delta[SS*LL*DI];
__device__ __align__(128) float g_bo[SS*LL*DM];
__device__ __align__(128) float g_fin[BB*LL*DM];

// split-bf16 activation/weight planes: [hi plane][lo plane], row-major
__device__ __align__(128) __nv_bfloat16 g_pa768 [2*M4*DM];   // fc1 input uses M4; in_proj uses first M2 rows/plane
__device__ __align__(128) __nv_bfloat16 g_pa1536[2*M4*DI];
__device__ __align__(128) __nv_bfloat16 g_pw_in [NLAYER*2*(2*DI)*DM];
__device__ __align__(128) __nv_bfloat16 g_pw_fc1[NLAYER*2*(2*DI)*DM];
__device__ __align__(128) __nv_bfloat16 g_pw_out[NLAYER*2*DM*DI];
__device__ __align__(128) __nv_bfloat16 g_pw_fc2[NLAYER*2*DM*DI];
__device__ __align__(128) __nv_bfloat16 g_pw_xp [NLAYER*2*XDP*DI];

__device__ __forceinline__ float siluf(float x){ return x/(1.f+__expf(-x)); }

__device__ __forceinline__ void split_bf16(float v, __nv_bfloat16& h, __nv_bfloat16& l){
  h = __float2bfloat16(v);
  l = __float2bfloat16(v - __bfloat162float(h));
}

// ---------------- elementwise kernels ----------------
__global__ void embed_kernel(const int* __restrict__ ids, const float* __restrict__ emb,
                             float* __restrict__ out){
  int i = blockIdx.x*blockDim.x+threadIdx.x;
  if(i>=BB*LL*DM) return;
  int d=i%DM; int t=i/DM;
  out[i] = emb[(size_t)ids[t]*DM + d];
}

// Fused: v = h (+res); resA[fwd]=resA[bwd-mirror]=v; LN(v) -> split-bf16 planes (FWD rows only).
__global__ void aug_ln_pack_kernel(const float* __restrict__ h, const float* __restrict__ res,
                                   float* __restrict__ resA, __nv_bfloat16* __restrict__ pk,
                                   const float* __restrict__ w, const float* __restrict__ bias,
                                   int use_res){
  int r = blockIdx.x;              // 0 .. BB*LL-1
  int b = r / LL, l = r % LL;
  size_t fbase = (size_t)(b*LL + l)*DM;
  size_t rbase = (size_t)((2+b)*LL + (LL-1-l))*DM;
  float v[3]; float s=0.f,s2=0.f;
  #pragma unroll
  for(int j=0;j<3;j++){
    int idx = threadIdx.x + j*256;
    float t = h[fbase+idx];
    if(use_res) t += res[fbase+idx];
    v[j]=t; s+=t; s2+=t*t;
    resA[fbase+idx]=t; resA[rbase+idx]=t;
  }
  #pragma unroll
  for(int o=16;o>0;o>>=1){ s+=__shfl_xor_sync(0xffffffffu,s,o); s2+=__shfl_xor_sync(0xffffffffu,s2,o); }
  __shared__ float sh[2][8];
  int wid=threadIdx.x>>5, lane=threadIdx.x&31;
  if(lane==0){ sh[0][wid]=s; sh[1][wid]=s2; }
  __syncthreads();
  if(threadIdx.x<32){
    float a = lane<8? sh[0][lane]:0.f;
    float b2= lane<8? sh[1][lane]:0.f;
    #pragma unroll
    for(int o=4;o>0;o>>=1){ a+=__shfl_xor_sync(0xffffffffu,a,o); b2+=__shfl_xor_sync(0xffffffffu,b2,o); }
    if(lane==0){ sh[0][0]=a; sh[1][0]=b2; }
  }
  __syncthreads();
  float mean = sh[0][0]*(1.f/DM);
  float var  = fmaxf(sh[1][0]*(1.f/DM) - mean*mean, 0.f);
  float inv  = rsqrtf(var + 1e-5f);
  #pragma unroll
  for(int j=0;j<3;j++){
    int idx = threadIdx.x + j*256;
    float o2 = (v[j]-mean)*inv*w[idx] + bias[idx];
    __nv_bfloat16 hh,ll; split_bf16(o2,hh,ll);
    pk[fbase+idx]=hh; pk[(size_t)M2*DM + fbase+idx]=ll;   // plane stride M2*DM (fwd-only GEMM)
  }
}

// Row LayerNorm over DM=768. Optional pre-add, optional fp32 sum writeback,
// optional fp32 out, optional packed split-bf16 out.
__global__ void ln_kernel(const float* __restrict__ in, const float* __restrict__ addin,
                          float* __restrict__ sumout, float* __restrict__ out,
                          __nv_bfloat16* __restrict__ pk, int planeN,
                          const float* __restrict__ w, const float* __restrict__ bias){
  int r = blockIdx.x;
  size_t base = (size_t)r*DM;
  float v[3]; float s=0.f,s2=0.f;
  #pragma unroll
  for(int j=0;j<3;j++){
    int idx = threadIdx.x + j*256;
    float t = in[base+idx];
    if(addin) t += addin[base+idx];
    v[j]=t; s+=t; s2+=t*t;
  }
  if(sumout){
    #pragma unroll
    for(int j=0;j<3;j++) sumout[base+threadIdx.x+j*256]=v[j];
  }
  #pragma unroll
  for(int o=16;o>0;o>>=1){ s+=__shfl_xor_sync(0xffffffffu,s,o); s2+=__shfl_xor_sync(0xffffffffu,s2,o); }
  __shared__ float sh[2][8];
  int wid=threadIdx.x>>5, lane=threadIdx.x&31;
  if(lane==0){ sh[0][wid]=s; sh[1][wid]=s2; }
  __syncthreads();
  if(threadIdx.x<32){
    float a = lane<8? sh[0][lane]:0.f;
    float b2= lane<8? sh[1][lane]:0.f;
    #pragma unroll
    for(int o=4;o>0;o>>=1){ a+=__shfl_xor_sync(0xffffffffu,a,o); b2+=__shfl_xor_sync(0xffffffffu,b2,o); }
    if(lane==0){ sh[0][0]=a; sh[1][0]=b2; }
  }
  __syncthreads();
  float mean = sh[0][0]*(1.f/DM);
  float var  = fmaxf(sh[1][0]*(1.f/DM) - mean*mean, 0.f);
  float inv  = rsqrtf(var + 1e-5f);
  #pragma unroll
  for(int j=0;j<3;j++){
    int idx = threadIdx.x + j*256;
    float o2 = (v[j]-mean)*inv*w[idx] + bias[idx];
    if(out) out[base+idx] = o2;
    if(pk){
      __nv_bfloat16 hh,ll; split_bf16(o2,hh,ll);
      pk[base+idx] = hh; pk[(size_t)planeN + base+idx] = ll;
    }
  }
}

// depthwise causal conv + silu over augmented batch, reading FWD-ONLY xz with
// mirrored indices for s>=2. Writes fp32 xc AND split-bf16 planes (x_proj GEMM input).
__global__ void conv_silu_pack_kernel(const float* __restrict__ xz, const float* __restrict__ w,
                                      const float* __restrict__ b, float* __restrict__ xc,
                                      __nv_bfloat16* __restrict__ pk){
  int i = blockIdx.x*blockDim.x+threadIdx.x;
  if(i>=SS*LL*DI) return;
  int d=i%DI; int l=(i/DI)%LL; int s=i/(DI*LL);
  float acc = b[d];
  if(s<2){
    const float* xin = xz + (size_t)s*LL*2*DI + d;
    #pragma unroll
    for(int j=0;j<4;j++){
      int ll=l-3+j;
      if(ll>=0) acc = fmaf(w[d*4+j], xin[(size_t)ll*2*DI], acc);
    }
  } else {
    const float* xin = xz + (size_t)(s-2)*LL*2*DI + d;   // mirrored fwd rows
    #pragma unroll
    for(int j=0;j<4;j++){
      int ll=l-3+j;
      if(ll>=0) acc = fmaf(w[d*4+j], xin[(size_t)(LL-1-ll)*2*DI], acc);
    }
  }
  float v = siluf(acc);
  xc[i] = v;
  __nv_bfloat16 hh,ll2; split_bf16(v,hh,ll2);
  pk[i]=hh; pk[(size_t)M4*DI + i]=ll2;
}

// selective scan: 4 threads per (s,d) channel, 4 states each; quad shfl reduce.
// FUSED gate: y_out = (scan_y) * silu(z), z read mirror-aware from fwd-only xz.
// q==0 thread writes split-bf16 planes (out_proj GEMM input).
__global__ void scan_gate_pack_kernel(const float* __restrict__ xc, const float* __restrict__ delta,
                                      const float* __restrict__ xd_all, const float* __restrict__ A_log,
                                      const float* __restrict__ Dp, const float* __restrict__ xz,
                                      __nv_bfloat16* __restrict__ pk){
  int t = blockIdx.x*blockDim.x + threadIdx.x;
  if(t >= SS*DI*4) return;
  const int q = t & 3;
  const int ch = t >> 2;
  const int d = ch % DI, s = ch / DI;
  float Ar[4];
  #pragma unroll
  for(int j=0;j<4;j++) Ar[j] = -__expf(A_log[d*NS + 4*q + j]);
  float a1 = -__expf(A_log[d*NS]);
  bool okl = true;
  #pragma unroll
  for(int j=0;j<4;j++){
    float expect = (4*q+j+1)*a1;
    okl = okl && (fabsf(Ar[j]-expect) <= 1e-5f*fabsf(expect));
  }
  unsigned bal = __ballot_sync(0xffffffffu, okl);
  int qb = (threadIdx.x & 31) & ~3;
  bool fast = (((bal >> qb) & 0xFu) == 0xFu);
  float Dv = Dp[d];
  float h0=0.f,h1=0.f,h2=0.f,h3=0.f;
  const float* up = xc    + (size_t)s*LL*DI + d;
  const float* dp = delta + (size_t)s*LL*DI + d;
  const float* xd = xd_all + (size_t)s*LL*XDP;
  // z pointer: fwd rows for s<2, mirrored for s>=2
  const int sb = (s<2)? s : (s-2);
  const float* zp = xz + (size_t)sb*LL*2*DI + DI + d;
  const bool mir = (s>=2);

  float dl = dp[0], u = up[0];
  float4 B4 = *(const float4*)(xd + DTR + 4*q);
  float4 C4 = *(const float4*)(xd + DTR + NS + 4*q);
  float zv = 0.f;
  if(q==0) zv = zp[(size_t)(mir? (LL-1) : 0)*2*DI];
  for(int l=0;l<LL;l++){
    float cdl=dl, cu=u, cz=zv; float4 cB=B4, cC=C4;
    if(l+1<LL){
      const float* nx = xd + (size_t)(l+1)*XDP;
      dl = dp[(size_t)(l+1)*DI]; u = up[(size_t)(l+1)*DI];
      B4 = *(const float4*)(nx + DTR + 4*q);
      C4 = *(const float4*)(nx + DTR + NS + 4*q);
      if(q==0) zv = zp[(size_t)(mir? (LL-2-l) : (l+1))*2*DI];
    }
    float du = cdl*cu;
    float dA0,dA1,dA2,dA3;
    if(fast){
      float e1 = __expf(cdl*a1);
      float e2=e1*e1, e3=e2*e1, e4=e2*e2;
      float base;
      if(q==0) base=1.f; else if(q==1) base=e4; else if(q==2) base=e4*e4; else base=e4*e4*e4;
      dA0=base*e1; dA1=base*e2; dA2=base*e3; dA3=base*e4;
    } else {
      dA0=__expf(cdl*Ar[0]); dA1=__expf(cdl*Ar[1]);
      dA2=__expf(cdl*Ar[2]); dA3=__expf(cdl*Ar[3]);
    }
    h0=fmaf(dA0,h0,du*cB.x); h1=fmaf(dA1,h1,du*cB.y);
    h2=fmaf(dA2,h2,du*cB.z); h3=fmaf(dA3,h3,du*cB.w);
    float part = fmaf(h0,cC.x, fmaf(h1,cC.y, fmaf(h2,cC.z, h3*cC.w)));
    part += __shfl_xor_sync(0xffffffffu, part, 1);
    part += __shfl_xor_sync(0xffffffffu, part, 2);
    if(q==0){
      float yv = fmaf(cu, Dv, part) * siluf(cz);
      __nv_bfloat16 hh,ll2; split_bf16(yv,hh,ll2);
      size_t i = ((size_t)s*LL + l)*DI + d;
      pk[i]=hh; pk[(size_t)M4*DI + i]=ll2;
    }
  }
}

// a*silu(gate) -> packed split-bf16 (for fc2 GEMM input)
__global__ void fc_gate_pack_kernel(const float* __restrict__ big, __nv_bfloat16* __restrict__ pk){
  int i=blockIdx.x*blockDim.x+threadIdx.x;
  if(i>=SS*LL*DI) return;
  int r=i/DI, j=i%DI;
  float a = big[(size_t)r*2*DI + j];
  float b = big[(size_t)r*2*DI + DI + j];
  float v = a*siluf(b);
  __nv_bfloat16 hh,ll; split_bf16(v,hh,ll);
  pk[i]=hh; pk[(size_t)M4*DI + i]=ll;
}

__global__ void combine_kernel(const float* __restrict__ lnx, const float* __restrict__ resA,
                               float* __restrict__ h, float* __restrict__ res){
  int i=blockIdx.x*blockDim.x+threadIdx.x;
  if(i>=BB*LL*DM) return;
  int d=i%DM; int l=(i/DM)%LL; int b=i/(DM*LL);
  size_t f = ((size_t)(b*LL+l))*DM+d;
  size_t r = ((size_t)((2+b)*LL+(LL-1-l)))*DM+d;
  h[i]   = lnx[f]+lnx[r];
  res[i] = resA[f]+resA[r];
}

__global__ void mean_kernel(const float* __restrict__ fin, float* __restrict__ out){
  int i=blockIdx.x*blockDim.x+threadIdx.x;
  if(i>=BB*DM) return;
  int b=i/DM, j=i%DM;
  float s=0.f;
  for(int l=0;l<LL;l++) s += fin[((size_t)(b*LL+l))*DM+j];
  out[i] = s*(1.f/LL);
}

// weight split-pack: fp32 [n] -> hi plane [n], lo plane [n]
__global__ void wpack_kernel(const float* __restrict__ src, __nv_bfloat16* __restrict__ dst, int n){
  int i=blockIdx.x*blockDim.x+threadIdx.x;
  if(i>=n) return;
  __nv_bfloat16 hh,ll; split_bf16(src[i],hh,ll);
  dst[i]=hh; dst[(size_t)n+i]=ll;
}

// x_proj weight: [XD][DI] -> padded [XDP][DI] split planes (rows >= XD are zero)
__global__ void wpack_pad_kernel(const float* __restrict__ src, __nv_bfloat16* __restrict__ dst){
  int i=blockIdx.x*blockDim.x+threadIdx.x;
  if(i>=XDP*DI) return;
  int row=i/DI, col=i%DI;
  float v = (row<XD) ? src[(size_t)row*DI+col] : 0.f;
  __nv_bfloat16 hh,ll; split_bf16(v,hh,ll);
  dst[i]=hh; dst[(size_t)XDP*DI+i]=ll;
}

// ---------------- HMMA (mma.sync bf16, split 3-pass) GEMM ----------------
__device__ __forceinline__ uint32_t smem_u32(const void* p){
  uint32_t a;
  asm("{ .reg .u64 t; cvta.to.shared.u64 t, %1; cvt.u32.u64 %0, t; }" : "=r"(a) : "l"(p));
  return a;
}
#define LDSM4(r, addr) \
  asm volatile("ldmatrix.sync.aligned.m8n8.x4.shared.b16 {%0,%1,%2,%3}, [%4];" \
    : "=r"((r)[0]),"=r"((r)[1]),"=r"((r)[2]),"=r"((r)[3]) : "r"(addr))
#define MMA16(d, a, b0, b1) \
  asm volatile("mma.sync.aligned.m16n8k16.row.col.f32.bf16.bf16.f32 " \
    "{%0,%1,%2,%3}, {%4,%5,%6,%7}, {%8,%9}, {%0,%1,%2,%3};" \
    : "+f"((d)[0]),"+f"((d)[1]),"+f"((d)[2]),"+f"((d)[3]) \
    : "r"((a)[0]),"r"((a)[1]),"r"((a)[2]),"r"((a)[3]), "r"(b0),"r"(b1))
#define CPA16(dst,src) asm volatile("cp.async.cg.shared.global [%0], [%1], 16;" :: "r"(dst), "l"(src))
#define CPCOMMIT() asm volatile("cp.async.commit_group;" ::: "memory")
#define CPWAIT2()  asm volatile("cp.async.wait_group 2;" ::: "memory")

#define HM_STAGES 4
#define HM_PLANE_BYTES 4096
#define HM_STAGE_BYTES 16384
#define HM_SMEM (HM_STAGES*HM_STAGE_BYTES)

__device__ __forceinline__ uint32_t hm_off(int row, int half){
  return (uint32_t)((row>>3)*256 + (row&7)*16 + half*128);
}

__global__ void __launch_bounds__(256) mm_hmma(
    int K, int N,
    const __nv_bfloat16* __restrict__ Ap,
    const __nv_bfloat16* __restrict__ Bp,
    float* __restrict__ C)
{
  extern __shared__ __align__(128) char smem_[];
  const int tid = threadIdx.x, wid = tid>>5, lane = tid&31;
  const int bm = blockIdx.y, bn = blockIdx.x;
  const size_t aplane = (size_t)gridDim.y*128*K;
  const size_t bplane = (size_t)N*K;
  uint32_t sbase = smem_u32(smem_);

  const int lrow = tid>>1, lhalf = tid&1;
  const __nv_bfloat16* gA = Ap + (size_t)(bm*128 + lrow)*K + lhalf*8;
  const __nv_bfloat16* gB = Bp + (size_t)(bn*128 + lrow)*K + lhalf*8;
  const uint32_t sdst = sbase + hm_off(lrow, lhalf);

  const int T = K>>4;
  const int warp_m = wid>>1, warp_n = wid&1;
  const int lq = lane&15, lh2 = lane>>4;
  uint32_t aoff[2], boff[4];
  #pragma unroll
  for(int mi=0;mi<2;mi++) aoff[mi] = hm_off(warp_m*32+mi*16+lq, lh2);
  #pragma unroll
  for(int j=0;j<4;j++)    boff[j]  = hm_off(warp_n*64+j*16+lq, lh2);

  float acc[2][8][4];
  #pragma unroll
  for(int mi=0;mi<2;mi++)
    #pragma unroll
    for(int f=0;f<8;f++)
      #pragma unroll
      for(int q=0;q<4;q++) acc[mi][f][q]=0.f;

  #pragma unroll
  for(int t=0;t<3;t++){
    uint32_t d = sdst + (uint32_t)t*HM_STAGE_BYTES;
    const __nv_bfloat16* a = gA + t*16;
    const __nv_bfloat16* b = gB + t*16;
    CPA16(d,                     a);
    CPA16(d +   HM_PLANE_BYTES,  a + aplane);
    CPA16(d + 2*HM_PLANE_BYTES,  b);
    CPA16(d + 3*HM_PLANE_BYTES,  b + bplane);
    CPCOMMIT();
  }

  for(int t=0;t<T;t++){
    CPWAIT2();
    __syncthreads();
    uint32_t st_ = sbase + (uint32_t)(t & (HM_STAGES-1))*HM_STAGE_BYTES;
    uint32_t ah[2][4], al[2][4], bh[4][4], bl[4][4];
    #pragma unroll
    for(int mi=0;mi<2;mi++){
      LDSM4(ah[mi], st_ + aoff[mi]);
      LDSM4(al[mi], st_ + HM_PLANE_BYTES + aoff[mi]);
    }
    #pragma unroll
    for(int j=0;j<4;j++){
      LDSM4(bh[j], st_ + 2*HM_PLANE_BYTES + boff[j]);
      LDSM4(bl[j], st_ + 3*HM_PLANE_BYTES + boff[j]);
    }
    #pragma unroll
    for(int mi=0;mi<2;mi++){
      #pragma unroll
      for(int f=0;f<8;f++){
        const int j=f>>1, sel=f&1;
        MMA16(acc[mi][f], ah[mi], bh[j][sel], bh[j][sel+2]);
        MMA16(acc[mi][f], ah[mi], bl[j][sel], bl[j][sel+2]);
        MMA16(acc[mi][f], al[mi], bh[j][sel], bh[j][sel+2]);
      }
    }
    int tn = t+3;
    if(tn < T){
      uint32_t d = sdst + (uint32_t)(tn & (HM_STAGES-1))*HM_STAGE_BYTES;
      const __nv_bfloat16* a = gA + tn*16;
      const __nv_bfloat16* b = gB + tn*16;
      CPA16(d,                     a);
      CPA16(d +   HM_PLANE_BYTES,  a + aplane);
      CPA16(d + 2*HM_PLANE_BYTES,  b);
      CPA16(d + 3*HM_PLANE_BYTES,  b + bplane);
    }
    CPCOMMIT();
  }

  const int tr = lane>>2, tc = (lane&3)*2;
  const int row0 = bm*128 + warp_m*32;
  const int col0 = bn*128 + warp_n*64;
  #pragma unroll
  for(int mi=0;mi<2;mi++){
    #pragma unroll
    for(int f=0;f<8;f++){
      float* c0 = C + (size_t)(row0+mi*16+tr)*N + col0 + f*8 + tc;
      float2 v0; v0.x=acc[mi][f][0]; v0.y=acc[mi][f][1];
      float2 v1; v1.x=acc[mi][f][2]; v1.y=acc[mi][f][3];
      *(float2*)c0 = v0;
      *(float2*)(c0 + 8*(size_t)N) = v1;
    }
  }
}

// ---------------- fallback FFMA GEMM (delta: K=48) ----------------
template<int BM,int BN,int TM,int TN,int BK>
__global__ void __launch_bounds__(256) gemm_nt(
    int M,int N,int K,int lda,
    const float* __restrict__ A, const float* __restrict__ Bw,
    float* __restrict__ C, const float* __restrict__ bias, int act)
{
  __shared__ float As[BK][BM];
  __shared__ float Bs[BK][BN];
  const int t  = threadIdx.x;
  const int bm = blockIdx.y*BM, bn = blockIdx.x*BN;
  const int TCOL = BN/TN;
  const int tx = t % TCOL, ty = t / TCOL;
  const int KQ = BK/4;
  float acc[TM][TN];
  #pragma unroll
  for(int i=0;i<TM;i++)
    #pragma unroll
    for(int j=0;j<TN;j++) acc[i][j]=0.f;

  for(int k0=0;k0<K;k0+=BK){
    for(int i=t;i<BM*KQ;i+=256){
      int row = i/KQ, kq = (i%KQ)*4;
      float4 v = *(const float4*)(A + (size_t)(bm+row)*lda + k0 + kq);
      As[kq][row]=v.x; As[kq+1][row]=v.y; As[kq+2][row]=v.z; As[kq+3][row]=v.w;
    }
    for(int i=t;i<BN*KQ;i+=256){
      int row = i/KQ, kq = (i%KQ)*4;
      int gn = bn+row;
      float4 v = make_float4(0.f,0.f,0.f,0.f);
      if(gn<N) v = *(const float4*)(Bw + (size_t)gn*K + k0 + kq);
      Bs[kq][row]=v.x; Bs[kq+1][row]=v.y; Bs[kq+2][row]=v.z; Bs[kq+3][row]=v.w;
    }
    __syncthreads();
    #pragma unroll
    for(int kk=0;kk<BK;kk++){
      float a[TM], b[TN];
      #pragma unroll
      for(int i=0;i<TM;i++) a[i]=As[kk][ty*TM+i];
      #pragma unroll
      for(int j=0;j<TN;j++) b[j]=Bs[kk][tx*TN+j];
      #pragma unroll
      for(int i=0;i<TM;i++)
        #pragma unroll
        for(int j=0;j<TN;j++) acc[i][j] = fmaf(a[i],b[j],acc[i][j]);
    }
    __syncthreads();
  }
  #pragma unroll
  for(int i=0;i<TM;i++){
    int gm = bm + ty*TM + i;
    #pragma unroll
    for(int j=0;j<TN;j++){
      int gn = bn + tx*TN + j;
      if(gn<N){
        float c = acc[i][j];
        if(bias) c += bias[gn];
        if(act==1) c = (c>20.f)? c : log1pf(__expf(c));
        C[(size_t)gm*N + gn] = c;
      }
    }
  }
}

// ---------------- launcher ----------------
extern "C" void kernel_launch(void* const* d_in, const int* in_sizes, int n_in,
                              void* d_out, int out_size){
  const int*   ids    = (const int*)  d_in[0];
  const float* emb    = (const float*)d_in[1];
  const float* norm_w = (const float*)d_in[2];
  const float* norm_b = (const float*)d_in[3];
  const float* in_proj= (const float*)d_in[4];
  const float* conv_w = (const float*)d_in[5];
  const float* conv_b = (const float*)d_in[6];
  const float* x_proj = (const float*)d_in[7];
  const float* dt_w   = (const float*)d_in[8];
  const float* dt_b   = (const float*)d_in[9];
  const float* A_log  = (const float*)d_in[10];
  const float* Dw     = (const float*)d_in[11];
  const float* out_proj=(const float*)d_in[12];
  const float* norm2_w= (const float*)d_in[13];
  const float* norm2_b= (const float*)d_in[14];
  const float* fc1    = (const float*)d_in[15];
  const float* fc2    = (const float*)d_in[16];
  const float* normf_w= (const float*)d_in[17];
  const float* normf_b= (const float*)d_in[18];
  float* out = (float*)d_out;

  float *p_h,*p_res,*p_resA,*p_x,*p_xz,*p_xc,*p_xdbl,*p_delta,*p_bo,*p_fin;
  __nv_bfloat16 *pa768,*pa1536,*pw_in,*pw_fc1,*pw_out,*pw_fc2,*pw_xp;
  cudaGetSymbolAddress((void**)&p_h,    g_h);
  cudaGetSymbolAddress((void**)&p_res,  g_res);
  cudaGetSymbolAddress((void**)&p_resA, g_resA);
  cudaGetSymbolAddress((void**)&p_x,    g_x);
  cudaGetSymbolAddress((void**)&p_xz,   g_xz);
  cudaGetSymbolAddress((void**)&p_xc,   g_xc);
  cudaGetSymbolAddress((void**)&p_xdbl, g_xdbl);
  cudaGetSymbolAddress((void**)&p_delta,g_delta);
  cudaGetSymbolAddress((void**)&p_bo,   g_bo);
  cudaGetSymbolAddress((void**)&p_fin,  g_fin);
  cudaGetSymbolAddress((void**)&pa768,  g_pa768);
  cudaGetSymbolAddress((void**)&pa1536, g_pa1536);
  cudaGetSymbolAddress((void**)&pw_in,  g_pw_in);
  cudaGetSymbolAddress((void**)&pw_fc1, g_pw_fc1);
  cudaGetSymbolAddress((void**)&pw_out, g_pw_out);
  cudaGetSymbolAddress((void**)&pw_fc2, g_pw_fc2);
  cudaGetSymbolAddress((void**)&pw_xp,  g_pw_xp);

  cudaFuncSetAttribute(mm_hmma, cudaFuncAttributeMaxDynamicSharedMemorySize, HM_SMEM);

  const int TP=256;
  // Launch order tuned so the ncu-captured launch (observed: my #4) is mm_hmma(in_proj L0).
  wpack_kernel<<<(2*DI*DM+TP-1)/TP,TP>>>(in_proj, pw_in, 2*DI*DM);                            // 1
  embed_kernel<<<(BB*LL*DM+TP-1)/TP,TP>>>(ids, emb, p_h);                                     // 2
  aug_ln_pack_kernel<<<BB*LL,256>>>(p_h, p_res, p_resA, pa768, norm_w, norm_b, 0);            // 3
  { dim3 g(2*DI/128, M2/128); mm_hmma<<<g,256,HM_SMEM>>>(DM, 2*DI, pa768, pw_in, p_xz); }     // 4 <- profile me
  // remaining weight packs (layer 0)
  wpack_kernel<<<(DM*DI+TP-1)/TP,TP>>>(out_proj, pw_out, DM*DI);
  wpack_kernel<<<(2*DI*DM+TP-1)/TP,TP>>>(fc1, pw_fc1, 2*DI*DM);
  wpack_kernel<<<(DM*DI+TP-1)/TP,TP>>>(fc2, pw_fc2, DM*DI);
  wpack_pad_kernel<<<(XDP*DI+TP-1)/TP,TP>>>(x_proj, pw_xp);

  for(int li=0; li<NLAYER; li++){
    const float* cw = conv_w  + (size_t)li*DI*4;
    const float* cb = conv_b  + (size_t)li*DI;
    const float* dw = dt_w    + (size_t)li*DI*DTR;
    const float* db = dt_b    + (size_t)li*DI;
    const float* al = A_log   + (size_t)li*DI*NS;
    const float* Dl = Dw      + (size_t)li*DI;
    const float* n2w= norm2_w + (size_t)li*DM;
    const float* n2b= norm2_b + (size_t)li*DM;
    const __nv_bfloat16* wF1 = pw_fc1 + (size_t)li*2*(2*DI)*DM;
    const __nv_bfloat16* wOu = pw_out + (size_t)li*2*DM*DI;
    const __nv_bfloat16* wF2 = pw_fc2 + (size_t)li*2*DM*DI;
    const __nv_bfloat16* wXp = pw_xp  + (size_t)li*2*XDP*DI;

    if(li==1){
      // layer-1 weight packs + aug/LN + in_proj GEMM
      wpack_kernel<<<(2*DI*DM+TP-1)/TP,TP>>>(in_proj + (size_t)1*2*DI*DM, pw_in  + (size_t)1*2*(2*DI)*DM, 2*DI*DM);
      wpack_kernel<<<(DM*DI+TP-1)/TP,TP>>>(out_proj + (size_t)1*DM*DI, pw_out + (size_t)1*2*DM*DI, DM*DI);
      wpack_kernel<<<(2*DI*DM+TP-1)/TP,TP>>>(fc1     + (size_t)1*2*DI*DM, pw_fc1 + (size_t)1*2*(2*DI)*DM, 2*DI*DM);
      wpack_kernel<<<(DM*DI+TP-1)/TP,TP>>>(fc2      + (size_t)1*DM*DI, pw_fc2 + (size_t)1*2*DM*DI, DM*DI);
      wpack_pad_kernel<<<(XDP*DI+TP-1)/TP,TP>>>(x_proj + (size_t)1*XD*DI, pw_xp + (size_t)1*2*XDP*DI);
      aug_ln_pack_kernel<<<BB*LL,256>>>(p_h, p_res, p_resA, pa768,
                                        norm_w + (size_t)1*DM, norm_b + (size_t)1*DM, 1);
      dim3 g(2*DI/128, M2/128);
      mm_hmma<<<g,256,HM_SMEM>>>(DM, 2*DI, pa768, pw_in + (size_t)1*2*(2*DI)*DM, p_xz);
    }

    // conv + silu + split-pack xc (mirror-aware, reads fwd-only xz)
    conv_silu_pack_kernel<<<(SS*LL*DI+TP-1)/TP,TP>>>(p_xz, cw, cb, p_xc, pa1536);

    // x_dbl(padded) = xc @ x_proj_pad^T  (HMMA, N=128)
    { dim3 g(1, M4/128); mm_hmma<<<g,256,HM_SMEM>>>(DI, XDP, pa1536, wXp, p_xdbl); }

    // delta = softplus(dt @ dt_w^T + dt_b)  (K=48, lda=XDP)
    { dim3 g(DI/128, M4/128); gemm_nt<128,128,8,8,16><<<g,256>>>(M4, DI, DTR, XDP, p_xdbl, dw, p_delta, db, 1); }

    // selective scan + gate + pack (feeds out_proj)
    scan_gate_pack_kernel<<<(SS*DI*4+127)/128,128>>>(p_xc, p_delta, p_xdbl, al, Dl, p_xz, pa1536);

    // mixer_out = y @ out_proj^T (HMMA)
    { dim3 g(DM/128, M4/128); mm_hmma<<<g,256,HM_SMEM>>>(DI, DM, pa1536, wOu, p_bo); }

    // res += mixer_out ; x2 = LN(res, norm2) -> packed (feeds fc1 only)
    ln_kernel<<<M4,256>>>(p_bo, p_resA, p_resA, nullptr, pa768, M4*DM, n2w, n2b);

    // fc1 (HMMA)
    { dim3 g(2*DI/128, M4/128); mm_hmma<<<g,256,HM_SMEM>>>(DM, 2*DI, pa768, wF1, p_xz); }

    // gated MLP -> packed (feeds fc2 only)
    fc_gate_pack_kernel<<<(SS*LL*DI+TP-1)/TP,TP>>>(p_xz, pa1536);

    // fc2 (HMMA)
    { dim3 g(DM/128, M4/128); mm_hmma<<<g,256,HM_SMEM>>>(DI, DM, pa1536, wF2, p_bo); }

    // final norm on block outputs (fp32 out), then fwd+reverse(bwd) combine
    ln_kernel<<<M4,256>>>(p_bo, nullptr, nullptr, p_x, nullptr, 0, normf_w, normf_b);
    combine_kernel<<<(BB*LL*DM+TP-1)/TP,TP>>>(p_x, p_resA, p_h, p_res);
  }

  ln_kernel<<<BB*LL,256>>>(p_h, p_res, nullptr, p_fin, nullptr, 0, normf_w, normf_b);
  mean_kernel<<<(BB*DM+TP-1)/TP,TP>>>(p_fin, out);
}

// round 11
// speedup vs baseline: 1.9374x; 1.0750x over previous
#include <cuda_runtime.h>
#include <cuda_bf16.h>
#include <math.h>
#include <stdint.h>

#define BB 2
#define LL 1024
#define DM 768
#define NLAYER 2
#define DI 1536
#define NS 16
#define DTR 48
#define XD 80           // DTR + 2*NS
#define XDP 128         // padded x_dbl width
#define SS 4            // augmented batch: [fwd b0, fwd b1, bwd b0, bwd b1]
#define M4 (SS*LL)      // 4096 rows (augmented)
#define M2 (2*LL)       // 2048 rows (fwd only, in_proj GEMM)

// ---------------- scratch (static __device__, no allocation) ----------------
__device__ __align__(128) float g_h[BB*LL*DM];
__device__ __align__(128) float g_res[BB*LL*DM];
__device__ __align__(128) float g_resA[SS*LL*DM];
__device__ __align__(128) float g_xz[M2*2*DI];          // fwd only
__device__ __align__(128) float g_xc[SS*LL*DI];
__device__ __align__(128) float g_xdbl[M4*XDP];
__device__ __align__(128) float g_delta[SS*LL*DI];
__device__ __align__(128) float g_bo[SS*LL*DM];
__device__ __align__(128) float g_fin[BB*LL*DM];

// split-bf16 activation/weight planes: [hi plane][lo plane], row-major
__device__ __align__(128) __nv_bfloat16 g_pa768 [2*M4*DM];
__device__ __align__(128) __nv_bfloat16 g_pa1536[2*M4*DI];
__device__ __align__(128) __nv_bfloat16 g_pw_in [NLAYER*2*(2*DI)*DM];
__device__ __align__(128) __nv_bfloat16 g_pw_fc1[NLAYER*2*(2*DI)*DM];
__device__ __align__(128) __nv_bfloat16 g_pw_out[NLAYER*2*DM*DI];
__device__ __align__(128) __nv_bfloat16 g_pw_fc2[NLAYER*2*DM*DI];
__device__ __align__(128) __nv_bfloat16 g_pw_xp [NLAYER*2*XDP*DI];

__device__ __forceinline__ float siluf(float x){ return x/(1.f+__expf(-x)); }

__device__ __forceinline__ void split_bf16(float v, __nv_bfloat16& h, __nv_bfloat16& l){
  h = __float2bfloat16(v);
  l = __float2bfloat16(v - __bfloat162float(h));
}

// ---------------- elementwise kernels ----------------
__global__ void embed_kernel(const int* __restrict__ ids, const float* __restrict__ emb,
                             float* __restrict__ out){
  int i = blockIdx.x*blockDim.x+threadIdx.x;
  if(i>=BB*LL*DM) return;
  int d=i%DM; int t=i/DM;
  out[i] = emb[(size_t)ids[t]*DM + d];
}

// Fused: v = h (+res); resA[fwd]=resA[bwd-mirror]=v; LN(v) -> split-bf16 planes (FWD rows only).
__global__ void aug_ln_pack_kernel(const float* __restrict__ h, const float* __restrict__ res,
                                   float* __restrict__ resA, __nv_bfloat16* __restrict__ pk,
                                   const float* __restrict__ w, const float* __restrict__ bias,
                                   int use_res){
  int r = blockIdx.x;              // 0 .. BB*LL-1
  int b = r / LL, l = r % LL;
  size_t fbase = (size_t)(b*LL + l)*DM;
  size_t rbase = (size_t)((2+b)*LL + (LL-1-l))*DM;
  float v[3]; float s=0.f,s2=0.f;
  #pragma unroll
  for(int j=0;j<3;j++){
    int idx = threadIdx.x + j*256;
    float t = h[fbase+idx];
    if(use_res) t += res[fbase+idx];
    v[j]=t; s+=t; s2+=t*t;
    resA[fbase+idx]=t; resA[rbase+idx]=t;
  }
  #pragma unroll
  for(int o=16;o>0;o>>=1){ s+=__shfl_xor_sync(0xffffffffu,s,o); s2+=__shfl_xor_sync(0xffffffffu,s2,o); }
  __shared__ float sh[2][8];
  int wid=threadIdx.x>>5, lane=threadIdx.x&31;
  if(lane==0){ sh[0][wid]=s; sh[1][wid]=s2; }
  __syncthreads();
  if(threadIdx.x<32){
    float a = lane<8? sh[0][lane]:0.f;
    float b2= lane<8? sh[1][lane]:0.f;
    #pragma unroll
    for(int o=4;o>0;o>>=1){ a+=__shfl_xor_sync(0xffffffffu,a,o); b2+=__shfl_xor_sync(0xffffffffu,b2,o); }
    if(lane==0){ sh[0][0]=a; sh[1][0]=b2; }
  }
  __syncthreads();
  float mean = sh[0][0]*(1.f/DM);
  float var  = fmaxf(sh[1][0]*(1.f/DM) - mean*mean, 0.f);
  float inv  = rsqrtf(var + 1e-5f);
  #pragma unroll
  for(int j=0;j<3;j++){
    int idx = threadIdx.x + j*256;
    float o2 = (v[j]-mean)*inv*w[idx] + bias[idx];
    __nv_bfloat16 hh,ll; split_bf16(o2,hh,ll);
    pk[fbase+idx]=hh; pk[(size_t)M2*DM + fbase+idx]=ll;
  }
}

// Row LayerNorm over DM=768. Optional pre-add, optional fp32 sum writeback,
// optional fp32 out, optional packed split-bf16 out.
__global__ void ln_kernel(const float* __restrict__ in, const float* __restrict__ addin,
                          float* __restrict__ sumout, float* __restrict__ out,
                          __nv_bfloat16* __restrict__ pk, int planeN,
                          const float* __restrict__ w, const float* __restrict__ bias){
  int r = blockIdx.x;
  size_t base = (size_t)r*DM;
  float v[3]; float s=0.f,s2=0.f;
  #pragma unroll
  for(int j=0;j<3;j++){
    int idx = threadIdx.x + j*256;
    float t = in[base+idx];
    if(addin) t += addin[base+idx];
    v[j]=t; s+=t; s2+=t*t;
  }
  if(sumout){
    #pragma unroll
    for(int j=0;j<3;j++) sumout[base+threadIdx.x+j*256]=v[j];
  }
  #pragma unroll
  for(int o=16;o>0;o>>=1){ s+=__shfl_xor_sync(0xffffffffu,s,o); s2+=__shfl_xor_sync(0xffffffffu,s2,o); }
  __shared__ float sh[2][8];
  int wid=threadIdx.x>>5, lane=threadIdx.x&31;
  if(lane==0){ sh[0][wid]=s; sh[1][wid]=s2; }
  __syncthreads();
  if(threadIdx.x<32){
    float a = lane<8? sh[0][lane]:0.f;
    float b2= lane<8? sh[1][lane]:0.f;
    #pragma unroll
    for(int o=4;o>0;o>>=1){ a+=__shfl_xor_sync(0xffffffffu,a,o); b2+=__shfl_xor_sync(0xffffffffu,b2,o); }
    if(lane==0){ sh[0][0]=a; sh[1][0]=b2; }
  }
  __syncthreads();
  float mean = sh[0][0]*(1.f/DM);
  float var  = fmaxf(sh[1][0]*(1.f/DM) - mean*mean, 0.f);
  float inv  = rsqrtf(var + 1e-5f);
  #pragma unroll
  for(int j=0;j<3;j++){
    int idx = threadIdx.x + j*256;
    float o2 = (v[j]-mean)*inv*w[idx] + bias[idx];
    if(out) out[base+idx] = o2;
    if(pk){
      __nv_bfloat16 hh,ll; split_bf16(o2,hh,ll);
      pk[base+idx] = hh; pk[(size_t)planeN + base+idx] = ll;
    }
  }
}

// Fused final-norm + bidirectional combine:
// each block handles fwd row f and its mirror bwd row rr:
//   h[f] = LNf(bo[f]) + LNf(bo[rr]);  res[f] = resA[f] + resA[rr]
__global__ void ln_combine_kernel(const float* __restrict__ bo, const float* __restrict__ resA,
                                  float* __restrict__ h, float* __restrict__ res,
                                  const float* __restrict__ w, const float* __restrict__ bias){
  int r = blockIdx.x;              // 0..BB*LL-1
  int b = r / LL, l = r % LL;
  size_t f  = (size_t)(b*LL + l)*DM;
  size_t rr = (size_t)((2+b)*LL + (LL-1-l))*DM;
  float vf[3], vr[3];
  float sf=0.f,s2f=0.f,sr=0.f,s2r=0.f;
  #pragma unroll
  for(int j=0;j<3;j++){
    int idx = threadIdx.x + j*256;
    float tf = bo[f+idx];  vf[j]=tf; sf+=tf; s2f+=tf*tf;
    float tr = bo[rr+idx]; vr[j]=tr; sr+=tr; s2r+=tr*tr;
  }
  #pragma unroll
  for(int o=16;o>0;o>>=1){
    sf+=__shfl_xor_sync(0xffffffffu,sf,o); s2f+=__shfl_xor_sync(0xffffffffu,s2f,o);
    sr+=__shfl_xor_sync(0xffffffffu,sr,o); s2r+=__shfl_xor_sync(0xffffffffu,s2r,o);
  }
  __shared__ float sh[4][8];
  int wid=threadIdx.x>>5, lane=threadIdx.x&31;
  if(lane==0){ sh[0][wid]=sf; sh[1][wid]=s2f; sh[2][wid]=sr; sh[3][wid]=s2r; }
  __syncthreads();
  if(threadIdx.x<32){
    float a0 = lane<8? sh[0][lane]:0.f;
    float a1 = lane<8? sh[1][lane]:0.f;
    float a2 = lane<8? sh[2][lane]:0.f;
    float a3 = lane<8? sh[3][lane]:0.f;
    #pragma unroll
    for(int o=4;o>0;o>>=1){
      a0+=__shfl_xor_sync(0xffffffffu,a0,o); a1+=__shfl_xor_sync(0xffffffffu,a1,o);
      a2+=__shfl_xor_sync(0xffffffffu,a2,o); a3+=__shfl_xor_sync(0xffffffffu,a3,o);
    }
    if(lane==0){ sh[0][0]=a0; sh[1][0]=a1; sh[2][0]=a2; sh[3][0]=a3; }
  }
  __syncthreads();
  float mf = sh[0][0]*(1.f/DM);
  float invf = rsqrtf(fmaxf(sh[1][0]*(1.f/DM)-mf*mf,0.f)+1e-5f);
  float mr = sh[2][0]*(1.f/DM);
  float invr = rsqrtf(fmaxf(sh[3][0]*(1.f/DM)-mr*mr,0.f)+1e-5f);
  #pragma unroll
  for(int j=0;j<3;j++){
    int idx = threadIdx.x + j*256;
    float of = (vf[j]-mf)*invf*w[idx] + bias[idx];
    float orr= (vr[j]-mr)*invr*w[idx] + bias[idx];
    h[f+idx]   = of + orr;
    res[f+idx] = resA[f+idx] + resA[rr+idx];
  }
}

// depthwise causal conv + silu over augmented batch, reading FWD-ONLY xz with
// mirrored indices for s>=2. Writes fp32 xc AND split-bf16 planes (x_proj GEMM input).
__global__ void conv_silu_pack_kernel(const float* __restrict__ xz, const float* __restrict__ w,
                                      const float* __restrict__ b, float* __restrict__ xc,
                                      __nv_bfloat16* __restrict__ pk){
  int i = blockIdx.x*blockDim.x+threadIdx.x;
  if(i>=SS*LL*DI) return;
  int d=i%DI; int l=(i/DI)%LL; int s=i/(DI*LL);
  float acc = b[d];
  if(s<2){
    const float* xin = xz + (size_t)s*LL*2*DI + d;
    #pragma unroll
    for(int j=0;j<4;j++){
      int ll=l-3+j;
      if(ll>=0) acc = fmaf(w[d*4+j], xin[(size_t)ll*2*DI], acc);
    }
  } else {
    const float* xin = xz + (size_t)(s-2)*LL*2*DI + d;   // mirrored fwd rows
    #pragma unroll
    for(int j=0;j<4;j++){
      int ll=l-3+j;
      if(ll>=0) acc = fmaf(w[d*4+j], xin[(size_t)(LL-1-ll)*2*DI], acc);
    }
  }
  float v = siluf(acc);
  xc[i] = v;
  __nv_bfloat16 hh,ll2; split_bf16(v,hh,ll2);
  pk[i]=hh; pk[(size_t)M4*DI + i]=ll2;
}

// selective scan: 4 threads per (s,d) channel, 4 states each; quad shfl reduce.
// FUSED gate: y_out = (scan_y) * silu(z), z read mirror-aware from fwd-only xz.
__global__ void scan_gate_pack_kernel(const float* __restrict__ xc, const float* __restrict__ delta,
                                      const float* __restrict__ xd_all, const float* __restrict__ A_log,
                                      const float* __restrict__ Dp, const float* __restrict__ xz,
                                      __nv_bfloat16* __restrict__ pk){
  int t = blockIdx.x*blockDim.x + threadIdx.x;
  if(t >= SS*DI*4) return;
  const int q = t & 3;
  const int ch = t >> 2;
  const int d = ch % DI, s = ch / DI;
  float Ar[4];
  #pragma unroll
  for(int j=0;j<4;j++) Ar[j] = -__expf(A_log[d*NS + 4*q + j]);
  float a1 = -__expf(A_log[d*NS]);
  bool okl = true;
  #pragma unroll
  for(int j=0;j<4;j++){
    float expect = (4*q+j+1)*a1;
    okl = okl && (fabsf(Ar[j]-expect) <= 1e-5f*fabsf(expect));
  }
  unsigned bal = __ballot_sync(0xffffffffu, okl);
  int qb = (threadIdx.x & 31) & ~3;
  bool fast = (((bal >> qb) & 0xFu) == 0xFu);
  float Dv = Dp[d];
  float h0=0.f,h1=0.f,h2=0.f,h3=0.f;
  const float* up = xc    + (size_t)s*LL*DI + d;
  const float* dp = delta + (size_t)s*LL*DI + d;
  const float* xd = xd_all + (size_t)s*LL*XDP;
  const int sb = (s<2)? s : (s-2);
  const float* zp = xz + (size_t)sb*LL*2*DI + DI + d;
  const bool mir = (s>=2);

  float dl = dp[0], u = up[0];
  float4 B4 = *(const float4*)(xd + DTR + 4*q);
  float4 C4 = *(const float4*)(xd + DTR + NS + 4*q);
  float zv = 0.f;
  if(q==0) zv = zp[(size_t)(mir? (LL-1) : 0)*2*DI];
  for(int l=0;l<LL;l++){
    float cdl=dl, cu=u, cz=zv; float4 cB=B4, cC=C4;
    if(l+1<LL){
      const float* nx = xd + (size_t)(l+1)*XDP;
      dl = dp[(size_t)(l+1)*DI]; u = up[(size_t)(l+1)*DI];
      B4 = *(const float4*)(nx + DTR + 4*q);
      C4 = *(const float4*)(nx + DTR + NS + 4*q);
      if(q==0) zv = zp[(size_t)(mir? (LL-2-l) : (l+1))*2*DI];
    }
    float du = cdl*cu;
    float dA0,dA1,dA2,dA3;
    if(fast){
      float e1 = __expf(cdl*a1);
      float e2=e1*e1, e3=e2*e1, e4=e2*e2;
      float base;
      if(q==0) base=1.f; else if(q==1) base=e4; else if(q==2) base=e4*e4; else base=e4*e4*e4;
      dA0=base*e1; dA1=base*e2; dA2=base*e3; dA3=base*e4;
    } else {
      dA0=__expf(cdl*Ar[0]); dA1=__expf(cdl*Ar[1]);
      dA2=__expf(cdl*Ar[2]); dA3=__expf(cdl*Ar[3]);
    }
    h0=fmaf(dA0,h0,du*cB.x); h1=fmaf(dA1,h1,du*cB.y);
    h2=fmaf(dA2,h2,du*cB.z); h3=fmaf(dA3,h3,du*cB.w);
    float part = fmaf(h0,cC.x, fmaf(h1,cC.y, fmaf(h2,cC.z, h3*cC.w)));
    part += __shfl_xor_sync(0xffffffffu, part, 1);
    part += __shfl_xor_sync(0xffffffffu, part, 2);
    if(q==0){
      float yv = fmaf(cu, Dv, part) * siluf(cz);
      __nv_bfloat16 hh,ll2; split_bf16(yv,hh,ll2);
      size_t i = ((size_t)s*LL + l)*DI + d;
      pk[i]=hh; pk[(size_t)M4*DI + i]=ll2;
    }
  }
}

// a*silu(gate) -> packed split-bf16 (for fc2 GEMM input)
__global__ void fc_gate_pack_kernel(const float* __restrict__ big, __nv_bfloat16* __restrict__ pk){
  int i=blockIdx.x*blockDim.x+threadIdx.x;
  if(i>=SS*LL*DI) return;
  int r=i/DI, j=i%DI;
  float a = big[(size_t)r*2*DI + j];
  float b = big[(size_t)r*2*DI + DI + j];
  float v = a*siluf(b);
  __nv_bfloat16 hh,ll; split_bf16(v,hh,ll);
  pk[i]=hh; pk[(size_t)M4*DI + i]=ll;
}

__global__ void mean_kernel(const float* __restrict__ fin, float* __restrict__ out){
  int i=blockIdx.x*blockDim.x+threadIdx.x;
  if(i>=BB*DM) return;
  int b=i/DM, j=i%DM;
  float s=0.f;
  for(int l=0;l<LL;l++) s += fin[((size_t)(b*LL+l))*DM+j];
  out[i] = s*(1.f/LL);
}

// weight split-pack: fp32 [n] -> hi plane [n], lo plane [n]
__global__ void wpack_kernel(const float* __restrict__ src, __nv_bfloat16* __restrict__ dst, int n){
  int i=blockIdx.x*blockDim.x+threadIdx.x;
  if(i>=n) return;
  __nv_bfloat16 hh,ll; split_bf16(src[i],hh,ll);
  dst[i]=hh; dst[(size_t)n+i]=ll;
}

// x_proj weight: [XD][DI] -> padded [XDP][DI] split planes (rows >= XD are zero)
__global__ void wpack_pad_kernel(const float* __restrict__ src, __nv_bfloat16* __restrict__ dst){
  int i=blockIdx.x*blockDim.x+threadIdx.x;
  if(i>=XDP*DI) return;
  int row=i/DI, col=i%DI;
  float v = (row<XD) ? src[(size_t)row*DI+col] : 0.f;
  __nv_bfloat16 hh,ll; split_bf16(v,hh,ll);
  dst[i]=hh; dst[(size_t)XDP*DI+i]=ll;
}

// ---------------- HMMA (mma.sync bf16, split 3-pass) GEMM ----------------
__device__ __forceinline__ uint32_t smem_u32(const void* p){
  uint32_t a;
  asm("{ .reg .u64 t; cvta.to.shared.u64 t, %1; cvt.u32.u64 %0, t; }" : "=r"(a) : "l"(p));
  return a;
}
#define LDSM4(r, addr) \
  asm volatile("ldmatrix.sync.aligned.m8n8.x4.shared.b16 {%0,%1,%2,%3}, [%4];" \
    : "=r"((r)[0]),"=r"((r)[1]),"=r"((r)[2]),"=r"((r)[3]) : "r"(addr))
#define MMA16(d, a, b0, b1) \
  asm volatile("mma.sync.aligned.m16n8k16.row.col.f32.bf16.bf16.f32 " \
    "{%0,%1,%2,%3}, {%4,%5,%6,%7}, {%8,%9}, {%0,%1,%2,%3};" \
    : "+f"((d)[0]),"+f"((d)[1]),"+f"((d)[2]),"+f"((d)[3]) \
    : "r"((a)[0]),"r"((a)[1]),"r"((a)[2]),"r"((a)[3]), "r"(b0),"r"(b1))
#define CPA16(dst,src) asm volatile("cp.async.cg.shared.global [%0], [%1], 16;" :: "r"(dst), "l"(src))
#define CPCOMMIT() asm volatile("cp.async.commit_group;" ::: "memory")
#define CPWAIT2()  asm volatile("cp.async.wait_group 2;" ::: "memory")

#define HM_STAGES 4
#define HM_PLANE_BYTES 4096
#define HM_STAGE_BYTES 16384
#define HM_SMEM (HM_STAGES*HM_STAGE_BYTES)

__device__ __forceinline__ uint32_t hm_off(int row, int half){
  return (uint32_t)((row>>3)*256 + (row&7)*16 + half*128);
}

__global__ void __launch_bounds__(256,2) mm_hmma(
    int K, int N,
    const __nv_bfloat16* __restrict__ Ap,
    const __nv_bfloat16* __restrict__ Bp,
    float* __restrict__ C)
{
  extern __shared__ __align__(128) char smem_[];
  const int tid = threadIdx.x, wid = tid>>5, lane = tid&31;
  const int bm = blockIdx.y, bn = blockIdx.x;
  const size_t aplane = (size_t)gridDim.y*128*K;
  const size_t bplane = (size_t)N*K;
  uint32_t sbase = smem_u32(smem_);

  const int lrow = tid>>1, lhalf = tid&1;
  const __nv_bfloat16* gA = Ap + (size_t)(bm*128 + lrow)*K + lhalf*8;
  const __nv_bfloat16* gB = Bp + (size_t)(bn*128 + lrow)*K + lhalf*8;
  const uint32_t sdst = sbase + hm_off(lrow, lhalf);

  const int T = K>>4;
  const int warp_m = wid>>1, warp_n = wid&1;
  const int lq = lane&15, lh2 = lane>>4;
  uint32_t aoff[2], boff[4];
  #pragma unroll
  for(int mi=0;mi<2;mi++) aoff[mi] = hm_off(warp_m*32+mi*16+lq, lh2);
  #pragma unroll
  for(int j=0;j<4;j++)    boff[j]  = hm_off(warp_n*64+j*16+lq, lh2);

  float acc[2][8][4];
  #pragma unroll
  for(int mi=0;mi<2;mi++)
    #pragma unroll
    for(int f=0;f<8;f++)
      #pragma unroll
      for(int q=0;q<4;q++) acc[mi][f][q]=0.f;

  #pragma unroll
  for(int t=0;t<3;t++){
    uint32_t d = sdst + (uint32_t)t*HM_STAGE_BYTES;
    const __nv_bfloat16* a = gA + t*16;
    const __nv_bfloat16* b = gB + t*16;
    CPA16(d,                     a);
    CPA16(d +   HM_PLANE_BYTES,  a + aplane);
    CPA16(d + 2*HM_PLANE_BYTES,  b);
    CPA16(d + 3*HM_PLANE_BYTES,  b + bplane);
    CPCOMMIT();
  }

  for(int t=0;t<T;t++){
    CPWAIT2();
    __syncthreads();
    uint32_t st_ = sbase + (uint32_t)(t & (HM_STAGES-1))*HM_STAGE_BYTES;
    // Phase 1: ah/al/bh resident, issue the 32 ·bh MMAs
    uint32_t ah[2][4], al[2][4], bb[4][4];
    #pragma unroll
    for(int mi=0;mi<2;mi++){
      LDSM4(ah[mi], st_ + aoff[mi]);
      LDSM4(al[mi], st_ + HM_PLANE_BYTES + aoff[mi]);
    }
    #pragma unroll
    for(int j=0;j<4;j++) LDSM4(bb[j], st_ + 2*HM_PLANE_BYTES + boff[j]);
    #pragma unroll
    for(int mi=0;mi<2;mi++){
      #pragma unroll
      for(int f=0;f<8;f++){
        const int j=f>>1, sel=f&1;
        MMA16(acc[mi][f], ah[mi], bb[j][sel], bb[j][sel+2]);
        MMA16(acc[mi][f], al[mi], bb[j][sel], bb[j][sel+2]);
      }
    }
    // Phase 2: overwrite b frags with bl, issue the 16 ah·bl MMAs
    #pragma unroll
    for(int j=0;j<4;j++) LDSM4(bb[j], st_ + 3*HM_PLANE_BYTES + boff[j]);
    #pragma unroll
    for(int mi=0;mi<2;mi++){
      #pragma unroll
      for(int f=0;f<8;f++){
        const int j=f>>1, sel=f&1;
        MMA16(acc[mi][f], ah[mi], bb[j][sel], bb[j][sel+2]);
      }
    }
    int tn = t+3;
    if(tn < T){
      uint32_t d = sdst + (uint32_t)(tn & (HM_STAGES-1))*HM_STAGE_BYTES;
      const __nv_bfloat16* a = gA + tn*16;
      const __nv_bfloat16* b = gB + tn*16;
      CPA16(d,                     a);
      CPA16(d +   HM_PLANE_BYTES,  a + aplane);
      CPA16(d + 2*HM_PLANE_BYTES,  b);
      CPA16(d + 3*HM_PLANE_BYTES,  b + bplane);
    }
    CPCOMMIT();
  }

  const int tr = lane>>2, tc = (lane&3)*2;
  const int row0 = bm*128 + warp_m*32;
  const int col0 = bn*128 + warp_n*64;
  #pragma unroll
  for(int mi=0;mi<2;mi++){
    #pragma unroll
    for(int f=0;f<8;f++){
      float* c0 = C + (size_t)(row0+mi*16+tr)*N + col0 + f*8 + tc;
      float2 v0; v0.x=acc[mi][f][0]; v0.y=acc[mi][f][1];
      float2 v1; v1.x=acc[mi][f][2]; v1.y=acc[mi][f][3];
      *(float2*)c0 = v0;
      *(float2*)(c0 + 8*(size_t)N) = v1;
    }
  }
}

// ---------------- fallback FFMA GEMM (delta: K=48) ----------------
template<int BM,int BN,int TM,int TN,int BK>
__global__ void __launch_bounds__(256) gemm_nt(
    int M,int N,int K,int lda,
    const float* __restrict__ A, const float* __restrict__ Bw,
    float* __restrict__ C, const float* __restrict__ bias, int act)
{
  __shared__ float As[BK][BM];
  __shared__ float Bs[BK][BN];
  const int t  = threadIdx.x;
  const int bm = blockIdx.y*BM, bn = blockIdx.x*BN;
  const int TCOL = BN/TN;
  const int tx = t % TCOL, ty = t / TCOL;
  const int KQ = BK/4;
  float acc[TM][TN];
  #pragma unroll
  for(int i=0;i<TM;i++)
    #pragma unroll
    for(int j=0;j<TN;j++) acc[i][j]=0.f;

  for(int k0=0;k0<K;k0+=BK){
    for(int i=t;i<BM*KQ;i+=256){
      int row = i/KQ, kq = (i%KQ)*4;
      float4 v = *(const float4*)(A + (size_t)(bm+row)*lda + k0 + kq);
      As[kq][row]=v.x; As[kq+1][row]=v.y; As[kq+2][row]=v.z; As[kq+3][row]=v.w;
    }
    for(int i=t;i<BN*KQ;i+=256){
      int row = i/KQ, kq = (i%KQ)*4;
      int gn = bn+row;
      float4 v = make_float4(0.f,0.f,0.f,0.f);
      if(gn<N) v = *(const float4*)(Bw + (size_t)gn*K + k0 + kq);
      Bs[kq][row]=v.x; Bs[kq+1][row]=v.y; Bs[kq+2][row]=v.z; Bs[kq+3][row]=v.w;
    }
    __syncthreads();
    #pragma unroll
    for(int kk=0;kk<BK;kk++){
      float a[TM], b[TN];
      #pragma unroll
      for(int i=0;i<TM;i++) a[i]=As[kk][ty*TM+i];
      #pragma unroll
      for(int j=0;j<TN;j++) b[j]=Bs[kk][tx*TN+j];
      #pragma unroll
      for(int i=0;i<TM;i++)
        #pragma unroll
        for(int j=0;j<TN;j++) acc[i][j] = fmaf(a[i],b[j],acc[i][j]);
    }
    __syncthreads();
  }
  #pragma unroll
  for(int i=0;i<TM;i++){
    int gm = bm + ty*TM + i;
    #pragma unroll
    for(int j=0;j<TN;j++){
      int gn = bn + tx*TN + j;
      if(gn<N){
        float c = acc[i][j];
        if(bias) c += bias[gn];
        if(act==1) c = (c>20.f)? c : log1pf(__expf(c));
        C[(size_t)gm*N + gn] = c;
      }
    }
  }
}

// ---------------- launcher ----------------
extern "C" void kernel_launch(void* const* d_in, const int* in_sizes, int n_in,
                              void* d_out, int out_size){
  const int*   ids    = (const int*)  d_in[0];
  const float* emb    = (const float*)d_in[1];
  const float* norm_w = (const float*)d_in[2];
  const float* norm_b = (const float*)d_in[3];
  const float* in_proj= (const float*)d_in[4];
  const float* conv_w = (const float*)d_in[5];
  const float* conv_b = (const float*)d_in[6];
  const float* x_proj = (const float*)d_in[7];
  const float* dt_w   = (const float*)d_in[8];
  const float* dt_b   = (const float*)d_in[9];
  const float* A_log  = (const float*)d_in[10];
  const float* Dw     = (const float*)d_in[11];
  const float* out_proj=(const float*)d_in[12];
  const float* norm2_w= (const float*)d_in[13];
  const float* norm2_b= (const float*)d_in[14];
  const float* fc1    = (const float*)d_in[15];
  const float* fc2    = (const float*)d_in[16];
  const float* normf_w= (const float*)d_in[17];
  const float* normf_b= (const float*)d_in[18];
  float* out = (float*)d_out;

  float *p_h,*p_res,*p_resA,*p_xz,*p_xc,*p_xdbl,*p_delta,*p_bo,*p_fin;
  __nv_bfloat16 *pa768,*pa1536,*pw_in,*pw_fc1,*pw_out,*pw_fc2,*pw_xp;
  cudaGetSymbolAddress((void**)&p_h,    g_h);
  cudaGetSymbolAddress((void**)&p_res,  g_res);
  cudaGetSymbolAddress((void**)&p_resA, g_resA);
  cudaGetSymbolAddress((void**)&p_xz,   g_xz);
  cudaGetSymbolAddress((void**)&p_xc,   g_xc);
  cudaGetSymbolAddress((void**)&p_xdbl, g_xdbl);
  cudaGetSymbolAddress((void**)&p_delta,g_delta);
  cudaGetSymbolAddress((void**)&p_bo,   g_bo);
  cudaGetSymbolAddress((void**)&p_fin,  g_fin);
  cudaGetSymbolAddress((void**)&pa768,  g_pa768);
  cudaGetSymbolAddress((void**)&pa1536, g_pa1536);
  cudaGetSymbolAddress((void**)&pw_in,  g_pw_in);
  cudaGetSymbolAddress((void**)&pw_fc1, g_pw_fc1);
  cudaGetSymbolAddress((void**)&pw_out, g_pw_out);
  cudaGetSymbolAddress((void**)&pw_fc2, g_pw_fc2);
  cudaGetSymbolAddress((void**)&pw_xp,  g_pw_xp);

  cudaFuncSetAttribute(mm_hmma, cudaFuncAttributeMaxDynamicSharedMemorySize, HM_SMEM);

  const int TP=256;
  // Launch order tuned so the ncu-captured launch (my #4) is mm_hmma(in_proj L0).
  wpack_kernel<<<(2*DI*DM+TP-1)/TP,TP>>>(in_proj, pw_in, 2*DI*DM);                            // 1
  embed_kernel<<<(BB*LL*DM+TP-1)/TP,TP>>>(ids, emb, p_h);                                     // 2
  aug_ln_pack_kernel<<<BB*LL,256>>>(p_h, p_res, p_resA, pa768, norm_w, norm_b, 0);            // 3
  { dim3 g(2*DI/128, M2/128); mm_hmma<<<g,256,HM_SMEM>>>(DM, 2*DI, pa768, pw_in, p_xz); }     // 4 <- profile me
  // remaining weight packs (layer 0)
  wpack_kernel<<<(DM*DI+TP-1)/TP,TP>>>(out_proj, pw_out, DM*DI);
  wpack_kernel<<<(2*DI*DM+TP-1)/TP,TP>>>(fc1, pw_fc1, 2*DI*DM);
  wpack_kernel<<<(DM*DI+TP-1)/TP,TP>>>(fc2, pw_fc2, DM*DI);
  wpack_pad_kernel<<<(XDP*DI+TP-1)/TP,TP>>>(x_proj, pw_xp);

  for(int li=0; li<NLAYER; li++){
    const float* cw = conv_w  + (size_t)li*DI*4;
    const float* cb = conv_b  + (size_t)li*DI;
    const float* dw = dt_w    + (size_t)li*DI*DTR;
    const float* db = dt_b    + (size_t)li*DI;
    const float* al = A_log   + (size_t)li*DI*NS;
    const float* Dl = Dw      + (size_t)li*DI;
    const float* n2w= norm2_w + (size_t)li*DM;
    const float* n2b= norm2_b + (size_t)li*DM;
    const __nv_bfloat16* wF1 = pw_fc1 + (size_t)li*2*(2*DI)*DM;
    const __nv_bfloat16* wOu = pw_out + (size_t)li*2*DM*DI;
    const __nv_bfloat16* wF2 = pw_fc2 + (size_t)li*2*DM*DI;
    const __nv_bfloat16* wXp = pw_xp  + (size_t)li*2*XDP*DI;

    if(li==1){
      wpack_kernel<<<(2*DI*DM+TP-1)/TP,TP>>>(in_proj + (size_t)1*2*DI*DM, pw_in  + (size_t)1*2*(2*DI)*DM, 2*DI*DM);
      wpack_kernel<<<(DM*DI+TP-1)/TP,TP>>>(out_proj + (size_t)1*DM*DI, pw_out + (size_t)1*2*DM*DI, DM*DI);
      wpack_kernel<<<(2*DI*DM+TP-1)/TP,TP>>>(fc1     + (size_t)1*2*DI*DM, pw_fc1 + (size_t)1*2*(2*DI)*DM, 2*DI*DM);
      wpack_kernel<<<(DM*DI+TP-1)/TP,TP>>>(fc2      + (size_t)1*DM*DI, pw_fc2 + (size_t)1*2*DM*DI, DM*DI);
      wpack_pad_kernel<<<(XDP*DI+TP-1)/TP,TP>>>(x_proj + (size_t)1*XD*DI, pw_xp + (size_t)1*2*XDP*DI);
      aug_ln_pack_kernel<<<BB*LL,256>>>(p_h, p_res, p_resA, pa768,
                                        norm_w + (size_t)1*DM, norm_b + (size_t)1*DM, 1);
      dim3 g(2*DI/128, M2/128);
      mm_hmma<<<g,256,HM_SMEM>>>(DM, 2*DI, pa768, pw_in + (size_t)1*2*(2*DI)*DM, p_xz);
    }

    // conv + silu + split-pack xc (mirror-aware, reads fwd-only xz)
    conv_silu_pack_kernel<<<(SS*LL*DI+TP-1)/TP,TP>>>(p_xz, cw, cb, p_xc, pa1536);

    // x_dbl(padded) = xc @ x_proj_pad^T  (HMMA, N=128)
    { dim3 g(1, M4/128); mm_hmma<<<g,256,HM_SMEM>>>(DI, XDP, pa1536, wXp, p_xdbl); }

    // delta = softplus(dt @ dt_w^T + dt_b)  (K=48, lda=XDP)
    { dim3 g(DI/128, M4/128); gemm_nt<128,128,8,8,16><<<g,256>>>(M4, DI, DTR, XDP, p_xdbl, dw, p_delta, db, 1); }

    // selective scan + gate + pack (feeds out_proj)
    scan_gate_pack_kernel<<<(SS*DI*4+127)/128,128>>>(p_xc, p_delta, p_xdbl, al, Dl, p_xz, pa1536);

    // mixer_out = y @ out_proj^T (HMMA)
    { dim3 g(DM/128, M4/128); mm_hmma<<<g,256,HM_SMEM>>>(DI, DM, pa1536, wOu, p_bo); }

    // res += mixer_out ; x2 = LN(res, norm2) -> packed (feeds fc1 only)
    ln_kernel<<<M4,256>>>(p_bo, p_resA, p_resA, nullptr, pa768, M4*DM, n2w, n2b);

    // fc1 (HMMA)
    { dim3 g(2*DI/128, M4/128); mm_hmma<<<g,256,HM_SMEM>>>(DM, 2*DI, pa768, wF1, p_xz); }

    // gated MLP -> packed (feeds fc2 only)
    fc_gate_pack_kernel<<<(SS*LL*DI+TP-1)/TP,TP>>>(p_xz, pa1536);

    // fc2 (HMMA)
    { dim3 g(DM/128, M4/128); mm_hmma<<<g,256,HM_SMEM>>>(DI, DM, pa1536, wF2, p_bo); }

    // fused final-norm + combine
    ln_combine_kernel<<<BB*LL,256>>>(p_bo, p_resA, p_h, p_res, normf_w, normf_b);
  }

  ln_kernel<<<BB*LL,256>>>(p_h, p_res, nullptr, p_fin, nullptr, 0, normf_w, normf_b);
  mean_kernel<<<(BB*DM+TP-1)/TP,TP>>>(p_fin, out);
}